// round 7
// baseline (speedup 1.0000x reference)
#include <cuda_runtime.h>
#include <cuda_fp16.h>
#include <cstdint>
#include <math.h>

// Problem dimensions (fixed by the reference)
#define BATCH 8
#define SEQ   8192
#define DIM   512
#define HID   512
#define OUTD  512
#define MROWS (BATCH*SEQ)      // 65536
#define CHUNK 128
#define NCH   (SEQ/CHUNK)      // 64

// ---------------------------------------------------------------------------
// Device scratch (no runtime allocation allowed)
// ---------------------------------------------------------------------------
static __device__ float g_lc[(size_t)MROWS*HID];        // log_coeffs
static __device__ float g_lv[(size_t)MROWS*HID];        // log_values
static __device__ float g_A  [(size_t)BATCH*NCH*HID];
static __device__ float g_LVc[(size_t)BATCH*NCH*HID];
static __device__ float g_hin[(size_t)BATCH*NCH*HID];
static __device__ __half g_xh [(size_t)MROWS*DIM];      // x  (fp16, single)
static __device__ __half g_hh [(size_t)MROWS*HID];      // h  (fp16, single)
static __device__ __half g_whh[(size_t)2*HID*DIM];      // W_hg hi
static __device__ __half g_whl[(size_t)2*HID*DIM];      // W_hg lo
static __device__ __half g_woh[(size_t)OUTD*HID];       // W_out hi
static __device__ __half g_wol[(size_t)OUTD*HID];       // W_out lo

// ---------------------------------------------------------------------------
// PTX helpers (sm_80+ only; no 'a'-suffix features)
// ---------------------------------------------------------------------------
__device__ __forceinline__ uint32_t smem_u32(const void* p) {
    uint32_t a;
    asm("{ .reg .u64 t; cvta.to.shared.u64 t, %1; cvt.u32.u64 %0, t; }" : "=r"(a) : "l"(p));
    return a;
}

#define CP_ASYNC16(dst, src) \
    asm volatile("cp.async.cg.shared.global [%0], [%1], 16;" :: "r"(dst), "l"(src))
#define CP_COMMIT() asm volatile("cp.async.commit_group;" ::: "memory")
#define CP_WAIT(N)  asm volatile("cp.async.wait_group %0;" :: "n"(N) : "memory")

#define LDMX4(r0, r1, r2, r3, a) \
    asm volatile("ldmatrix.sync.aligned.m8n8.x4.shared.b16 {%0,%1,%2,%3}, [%4];" \
        : "=r"(r0), "=r"(r1), "=r"(r2), "=r"(r3) : "r"(a))

// fp16 MMA, fp32 accumulate
#define MMA16816(c0, c1, c2, c3, a0, a1, a2, a3, b0, b1) \
    asm volatile("mma.sync.aligned.m16n8k16.row.col.f32.f16.f16.f32 " \
        "{%0,%1,%2,%3}, {%4,%5,%6,%7}, {%8,%9}, {%0,%1,%2,%3};" \
        : "+f"(c0), "+f"(c1), "+f"(c2), "+f"(c3) \
        : "r"(a0), "r"(a1), "r"(a2), "r"(a3), "r"(b0), "r"(b1))

// ---------------------------------------------------------------------------
// Math helpers
// ---------------------------------------------------------------------------
__device__ __forceinline__ float sp_f(float x) {
    return fmaxf(x, 0.0f) + log1pf(__expf(-fabsf(x)));
}
__device__ __forceinline__ float lae(float a, float b) {
    float m = fmaxf(a, b);
    return m + log1pf(__expf(-fabsf(a - b)));
}

// ---------------------------------------------------------------------------
// fp32 -> fp16 conversions
// ---------------------------------------------------------------------------
__global__ __launch_bounds__(256) void cvt_half(const float* __restrict__ src,
                                                __half* __restrict__ dst) {
    const size_t i = (size_t)blockIdx.x * blockDim.x + threadIdx.x;
    float4 v = ((const float4*)src)[i];
    ((__half2*)dst)[2*i]   = __floats2half2_rn(v.x, v.y);
    ((__half2*)dst)[2*i+1] = __floats2half2_rn(v.z, v.w);
}

__global__ __launch_bounds__(256) void cvt_split(const float* __restrict__ src,
                                                 __half* __restrict__ hi,
                                                 __half* __restrict__ lo) {
    const size_t i = (size_t)blockIdx.x * blockDim.x + threadIdx.x;
    float4 v = ((const float4*)src)[i];
    __half hx = __float2half_rn(v.x), hy = __float2half_rn(v.y);
    __half hz = __float2half_rn(v.z), hw = __float2half_rn(v.w);
    __half lx = __float2half_rn(v.x - __half2float(hx));
    __half ly = __float2half_rn(v.y - __half2float(hy));
    __half lz = __float2half_rn(v.z - __half2float(hz));
    __half lw = __float2half_rn(v.w - __half2float(hw));
    ((__half2*)hi)[2*i]   = __halves2half2(hx, hy);
    ((__half2*)hi)[2*i+1] = __halves2half2(hz, hw);
    ((__half2*)lo)[2*i]   = __halves2half2(lx, ly);
    ((__half2*)lo)[2*i+1] = __halves2half2(lz, lw);
}

// ---------------------------------------------------------------------------
// mma.sync GEMM mainloop. Block 128Mx128N, 256 threads (8 warps, warp tile
// 64x32), K=512, kc=32, double-buffered cp.async, 2 CTAs/SM. Precision:
// acc += A*Bhi + A*Blo  (A single fp16, B split fp16 hi/lo, fp32 acc).
//
// SMEM stage layout (bytes from stage base), row stride 80B (40 fp16):
//   A [0,10240)  Bhi [10240,20480)  Blo [20480,30720)
// Stage = 30720B, 2 stages = 61440B (gemm1 epilogue staging needs 77824).
//
// INTERLEAVE (GEMM1): B-tile n-row r maps to W_hg row (r even: nb + r/2
// hidden; r odd: 512 + nb + r/2 gate) so accumulator col pairs are
// (hidden, gate) of the same channel.
// ---------------------------------------------------------------------------
#define STG_B   30720
#define SMEM_BYTES 77824

template<bool INTERLEAVE>
__device__ __forceinline__ void gemm_mainloop(const __half* __restrict__ A,
                                              const __half* __restrict__ Bhi,
                                              const __half* __restrict__ Blo,
                                              int m0, int nb, uint32_t sbase,
                                              float acc[4][4][4]) {
    const int tid  = threadIdx.x;
    const int lane = tid & 31;
    const int wid  = tid >> 5;
    const int wm   = (wid >> 2) * 64;   // warp M offset (0/64)
    const int wn   = (wid & 3) * 32;    // warp N offset (0/32/64/96)

#pragma unroll
    for (int mi = 0; mi < 4; mi++)
#pragma unroll
        for (int ni = 0; ni < 4; ni++)
#pragma unroll
            for (int e = 0; e < 4; e++) acc[mi][ni][e] = 0.0f;

    // ---- stage loader: 6 cp.asyncs per thread ----
    auto load_stage = [&](int j, int s) {
        const uint32_t st = sbase + s * STG_B;
        const int k0 = j * 32;
#pragma unroll
        for (int i = 0; i < 2; i++) {
            const int idx = tid + i * 256;
            const int r = idx >> 2, c = idx & 3;
            const uint32_t so = (uint32_t)(r * 80 + c * 16);
            const size_t goa = (size_t)(m0 + r) * 512 + k0 + c * 8;
            CP_ASYNC16(st + so, (const void*)(A + goa));
            int wr;
            if (INTERLEAVE) wr = (r & 1) ? (512 + nb + (r >> 1)) : (nb + (r >> 1));
            else            wr = nb + r;
            const size_t gob = (size_t)wr * 512 + k0 + c * 8;
            CP_ASYNC16(st + 10240 + so, (const void*)(Bhi + gob));
            CP_ASYNC16(st + 20480 + so, (const void*)(Blo + gob));
        }
        CP_COMMIT();
    };

    load_stage(0, 0);

    for (int j = 0; j < 16; j++) {
        if (j + 1 < 16) load_stage(j + 1, (j + 1) & 1);
        if (j + 1 < 16) { CP_WAIT(1); } else { CP_WAIT(0); }
        __syncthreads();

        const uint32_t st = sbase + (j & 1) * STG_B;
#pragma unroll
        for (int s = 0; s < 2; s++) {          // two k16 steps per stage
            // ---- B fragments: 4 n8 tiles, hi+lo ----
            uint32_t bh[4][2], bl[4][2];
#pragma unroll
            for (int p = 0; p < 2; p++) {
                const int nr = wn + p * 16 + (lane & 7) + ((lane & 16) ? 8 : 0);
                const int ko = s * 16 + ((lane & 8) ? 8 : 0);
                const uint32_t ba = st + 10240 + (uint32_t)(nr * 80 + ko * 2);
                LDMX4(bh[p*2][0], bh[p*2][1], bh[p*2+1][0], bh[p*2+1][1], ba);
                LDMX4(bl[p*2][0], bl[p*2][1], bl[p*2+1][0], bl[p*2+1][1], ba + 10240);
            }
            // ---- A fragments per m-tile + MMAs ----
#pragma unroll
            for (int mi = 0; mi < 4; mi++) {
                const int mr = wm + mi * 16 + (lane & 15);
                const int ko = s * 16 + ((lane & 16) ? 8 : 0);
                const uint32_t aa = st + (uint32_t)(mr * 80 + ko * 2);
                uint32_t ah[4];
                LDMX4(ah[0], ah[1], ah[2], ah[3], aa);
#pragma unroll
                for (int ni = 0; ni < 4; ni++) {
                    MMA16816(acc[mi][ni][0], acc[mi][ni][1], acc[mi][ni][2], acc[mi][ni][3],
                             ah[0], ah[1], ah[2], ah[3], bh[ni][0], bh[ni][1]);
                    MMA16816(acc[mi][ni][0], acc[mi][ni][1], acc[mi][ni][2], acc[mi][ni][3],
                             ah[0], ah[1], ah[2], ah[3], bl[ni][0], bl[ni][1]);
                }
            }
        }
        __syncthreads();
    }
}

// ---------------------------------------------------------------------------
// GEMM1: hg = x @ W_hg^T with fused lc/lv epilogue (interleaved channels).
// Grid: (HID/64, MROWS/128). Each block: 128 rows x 64 channels.
// ---------------------------------------------------------------------------
__global__ __launch_bounds__(256, 2)
void gemm1_mma() {
    extern __shared__ __align__(128) char smem[];
    const uint32_t sbase = smem_u32(smem);
    const int m0 = blockIdx.y * 128;
    const int nb = blockIdx.x * 64;

    float acc[4][4][4];
    gemm_mainloop<true>(g_xh, g_whh, g_whl, m0, nb, sbase, acc);

    // Epilogue: compute lc/lv in regs, stage via smem (stride 76 floats),
    // then coalesced float4 writes.
    float* lcs = (float*)smem;            // [128][76]
    float* lvs = lcs + 128 * 76;          // [128][76]
    const int tid = threadIdx.x, lane = tid & 31, wid = tid >> 5;
    const int wm = (wid >> 2) * 64;
    const int wn = (wid & 3) * 32;

#pragma unroll
    for (int mi = 0; mi < 4; mi++) {
#pragma unroll
        for (int ni = 0; ni < 4; ni++) {
            const int j  = (wn >> 1) + ni * 4 + (lane & 3);   // channel 0..63
            const int r0 = wm + mi * 16 + (lane >> 2);
#pragma unroll
            for (int e = 0; e < 2; e++) {
                const int r = r0 + e * 8;
                const float hv = acc[mi][ni][2*e];
                const float gv = acc[mi][ni][2*e + 1];
                const float lgv = (hv >= 0.0f) ? __logf(hv + 0.5f) : -sp_f(-hv);
                lcs[r * 76 + j] = -sp_f(gv);
                lvs[r * 76 + j] = lgv - sp_f(-gv);
            }
        }
    }
    __syncthreads();

    for (int idx = tid; idx < 2048; idx += 256) {
        const int r = idx >> 4, q = idx & 15;
        const size_t go = (size_t)(m0 + r) * HID + nb + q * 4;
        *(float4*)(g_lc + go) = *(float4*)&lcs[r * 76 + q * 4];
        *(float4*)(g_lv + go) = *(float4*)&lvs[r * 76 + q * 4];
    }
}

// ---------------------------------------------------------------------------
// GEMM2: out = h @ W_out^T. Grid: (OUTD/128, MROWS/128). Direct f32x2 stores.
// ---------------------------------------------------------------------------
__global__ __launch_bounds__(256, 2)
void gemm2_mma(float* __restrict__ out) {
    extern __shared__ __align__(128) char smem[];
    const uint32_t sbase = smem_u32(smem);
    const int m0 = blockIdx.y * 128;
    const int nb = blockIdx.x * 128;

    float acc[4][4][4];
    gemm_mainloop<false>(g_hh, g_woh, g_wol, m0, nb, sbase, acc);

    const int tid = threadIdx.x, lane = tid & 31, wid = tid >> 5;
    const int wm = (wid >> 2) * 64;
    const int wn = (wid & 3) * 32;

#pragma unroll
    for (int mi = 0; mi < 4; mi++) {
#pragma unroll
        for (int ni = 0; ni < 4; ni++) {
            const int col = nb + wn + ni * 8 + (lane & 3) * 2;
            const int r0  = m0 + wm + mi * 16 + (lane >> 2);
            *(float2*)(out + (size_t)r0 * OUTD + col)
                = make_float2(acc[mi][ni][0], acc[mi][ni][1]);
            *(float2*)(out + (size_t)(r0 + 8) * OUTD + col)
                = make_float2(acc[mi][ni][2], acc[mi][ni][3]);
        }
    }
}

// ---------------------------------------------------------------------------
// Chunked log-space scan (pass3 emits fp16 h for GEMM2's A operand)
// ---------------------------------------------------------------------------
__global__ __launch_bounds__(512) void scan_pass1() {
    const int b = blockIdx.y, c = blockIdx.x, h = threadIdx.x;
    size_t base = ((size_t)(b * SEQ + c * CHUNK)) * HID + h;
    float A = 0.0f, LV = -1e30f;
    for (int t = 0; t < CHUNK; t++) {
        const float lc = g_lc[base];
        const float lv = g_lv[base];
        LV = lae(lc + LV, lv);
        A += lc;
        base += HID;
    }
    const size_t si = ((size_t)(b * NCH + c)) * HID + h;
    g_A[si]   = A;
    g_LVc[si] = LV;
}

__global__ __launch_bounds__(512) void scan_pass2() {
    const int b = blockIdx.x, h = threadIdx.x;
    float run = -1e30f;
    for (int c = 0; c < NCH; c++) {
        const size_t si = ((size_t)(b * NCH + c)) * HID + h;
        g_hin[si] = run;
        run = lae(g_A[si] + run, g_LVc[si]);
    }
}

__global__ __launch_bounds__(512) void scan_pass3(float* __restrict__ out_hn) {
    const int b = blockIdx.y, c = blockIdx.x, h = threadIdx.x;
    const size_t si = ((size_t)(b * NCH + c)) * HID + h;
    float lh = g_hin[si];
    size_t base = ((size_t)(b * SEQ + c * CHUNK)) * HID + h;
    float hv = 0.0f;
    for (int t = 0; t < CHUNK; t++) {
        lh = lae(g_lc[base] + lh, g_lv[base]);
        hv = __expf(lh);
        g_hh[base] = __float2half_rn(hv);
        base += HID;
    }
    if (c == NCH - 1)
        out_hn[b * HID + h] = hv;
}

// ---------------------------------------------------------------------------
// Launch. Inputs: x f32 (8,8192,512) | is_init bool(8) | W_hg f32 (1024,512)
// | W_out f32 (512,512). Output: out f32 (B,S,O) ++ h_n f32 (B,1,H).
// ---------------------------------------------------------------------------
extern "C" void kernel_launch(void* const* d_in, const int* in_sizes, int n_in,
                              void* d_out, int out_size) {
    (void)in_sizes; (void)n_in; (void)out_size;
    const float* x    = (const float*)d_in[0];
    const float* Whg  = (const float*)d_in[2];
    const float* Wout = (const float*)d_in[3];
    float* out    = (float*)d_out;
    float* out_hn = out + (size_t)MROWS * OUTD;

    cudaFuncSetAttribute((const void*)gemm1_mma,
                         cudaFuncAttributeMaxDynamicSharedMemorySize, SMEM_BYTES);
    cudaFuncSetAttribute((const void*)gemm2_mma,
                         cudaFuncAttributeMaxDynamicSharedMemorySize, SMEM_BYTES);

    __half *xh, *whh, *whl, *woh, *wol;
    cudaGetSymbolAddress((void**)&xh,  g_xh);
    cudaGetSymbolAddress((void**)&whh, g_whh);
    cudaGetSymbolAddress((void**)&whl, g_whl);
    cudaGetSymbolAddress((void**)&woh, g_woh);
    cudaGetSymbolAddress((void**)&wol, g_wol);

    // fp16 conversion prepass (x: single; weights: hi/lo split)
    cvt_half <<<(MROWS * (size_t)DIM) / 4 / 256, 256>>>(x, xh);
    cvt_split<<<(2 * HID * (size_t)DIM) / 4 / 256, 256>>>(Whg, whh, whl);
    cvt_split<<<(OUTD * (size_t)HID) / 4 / 256, 256>>>(Wout, woh, wol);

    // GEMM1 (mma.sync fp16, 2-product) with fused lc/lv epilogue
    gemm1_mma<<<dim3(HID / 64, MROWS / 128), 256, SMEM_BYTES>>>();

    // scan
    scan_pass1<<<dim3(NCH, BATCH), HID>>>();
    scan_pass2<<<BATCH, HID>>>();
    scan_pass3<<<dim3(NCH, BATCH), HID>>>(out_hn);

    // GEMM2 (mma.sync fp16, 2-product)
    gemm2_mma<<<dim3(OUTD / 128, MROWS / 128), 256, SMEM_BYTES>>>(out);
}

// round 8
// speedup vs baseline: 1.5609x; 1.5609x over previous
#include <cuda_runtime.h>
#include <cuda_fp16.h>
#include <cstdint>
#include <math.h>

// Problem dimensions (fixed by the reference)
#define BATCH 8
#define SEQ   8192
#define DIM   512
#define HID   512
#define OUTD  512
#define MROWS (BATCH*SEQ)      // 65536
#define CHUNK 128
#define NCH   (SEQ/CHUNK)      // 64

// ---------------------------------------------------------------------------
// Device scratch (no runtime allocation allowed)
// ---------------------------------------------------------------------------
static __device__ float g_lc[(size_t)MROWS*HID];        // log_coeffs
static __device__ float g_lv[(size_t)MROWS*HID];        // log_values
static __device__ float g_A  [(size_t)BATCH*NCH*HID];
static __device__ float g_LVc[(size_t)BATCH*NCH*HID];
static __device__ float g_hin[(size_t)BATCH*NCH*HID];
static __device__ __half g_xh [(size_t)MROWS*DIM];      // x  (fp16, single)
static __device__ __half g_hh [(size_t)MROWS*HID];      // h  (fp16, single)
static __device__ __half g_whh[(size_t)2*HID*DIM];      // W_hg hi
static __device__ __half g_whl[(size_t)2*HID*DIM];      // W_hg lo
static __device__ __half g_woh[(size_t)OUTD*HID];       // W_out hi
static __device__ __half g_wol[(size_t)OUTD*HID];       // W_out lo

// ---------------------------------------------------------------------------
// PTX helpers (sm_80+ only; no 'a'-suffix features)
// ---------------------------------------------------------------------------
__device__ __forceinline__ uint32_t smem_u32(const void* p) {
    uint32_t a;
    asm("{ .reg .u64 t; cvta.to.shared.u64 t, %1; cvt.u32.u64 %0, t; }" : "=r"(a) : "l"(p));
    return a;
}

#define CP_ASYNC16(dst, src) \
    asm volatile("cp.async.cg.shared.global [%0], [%1], 16;" :: "r"(dst), "l"(src))
#define CP_COMMIT() asm volatile("cp.async.commit_group;" ::: "memory")
#define CP_WAIT(N)  asm volatile("cp.async.wait_group %0;" :: "n"(N) : "memory")

#define LDMX4(r0, r1, r2, r3, a) \
    asm volatile("ldmatrix.sync.aligned.m8n8.x4.shared.b16 {%0,%1,%2,%3}, [%4];" \
        : "=r"(r0), "=r"(r1), "=r"(r2), "=r"(r3) : "r"(a))

// fp16 MMA, fp32 accumulate
#define MMA16816(c0, c1, c2, c3, a0, a1, a2, a3, b0, b1) \
    asm volatile("mma.sync.aligned.m16n8k16.row.col.f32.f16.f16.f32 " \
        "{%0,%1,%2,%3}, {%4,%5,%6,%7}, {%8,%9}, {%0,%1,%2,%3};" \
        : "+f"(c0), "+f"(c1), "+f"(c2), "+f"(c3) \
        : "r"(a0), "r"(a1), "r"(a2), "r"(a3), "r"(b0), "r"(b1))

// ---------------------------------------------------------------------------
// Math helpers
// ---------------------------------------------------------------------------
__device__ __forceinline__ float sp_f(float x) {
    return fmaxf(x, 0.0f) + log1pf(__expf(-fabsf(x)));
}
__device__ __forceinline__ float lae(float a, float b) {
    float m = fmaxf(a, b);
    return m + log1pf(__expf(-fabsf(a - b)));
}

// ---------------------------------------------------------------------------
// fp32 -> fp16 conversions
// ---------------------------------------------------------------------------
__global__ __launch_bounds__(256) void cvt_half(const float* __restrict__ src,
                                                __half* __restrict__ dst) {
    const size_t i = (size_t)blockIdx.x * blockDim.x + threadIdx.x;
    float4 v = ((const float4*)src)[i];
    ((__half2*)dst)[2*i]   = __floats2half2_rn(v.x, v.y);
    ((__half2*)dst)[2*i+1] = __floats2half2_rn(v.z, v.w);
}

__global__ __launch_bounds__(256) void cvt_split(const float* __restrict__ src,
                                                 __half* __restrict__ hi,
                                                 __half* __restrict__ lo) {
    const size_t i = (size_t)blockIdx.x * blockDim.x + threadIdx.x;
    float4 v = ((const float4*)src)[i];
    __half hx = __float2half_rn(v.x), hy = __float2half_rn(v.y);
    __half hz = __float2half_rn(v.z), hw = __float2half_rn(v.w);
    __half lx = __float2half_rn(v.x - __half2float(hx));
    __half ly = __float2half_rn(v.y - __half2float(hy));
    __half lz = __float2half_rn(v.z - __half2float(hz));
    __half lw = __float2half_rn(v.w - __half2float(hw));
    ((__half2*)hi)[2*i]   = __halves2half2(hx, hy);
    ((__half2*)hi)[2*i+1] = __halves2half2(hz, hw);
    ((__half2*)lo)[2*i]   = __halves2half2(lx, ly);
    ((__half2*)lo)[2*i+1] = __halves2half2(lz, lw);
}

// ---------------------------------------------------------------------------
// mma.sync GEMM mainloop. Block 128Mx128N, 256 threads (8 warps, warp tile
// 64x32), K=512, kc=64, double-buffered cp.async, 2 CTAs/SM. Precision:
// acc += A*Bhi + A*Blo  (A single fp16, B split fp16 hi/lo, fp32 acc).
//
// SMEM stage layout (bytes from stage base), row stride 144B (64 fp16 data
// + 16B pad; conflict-free for cp.async stores and ldmatrix reads):
//   A [0,18432)  Bhi [18432,36864)  Blo [36864,55296)
// Stage = 55296B, 2 stages = 110592B; 2 CTAs/SM = 216KB < 227KB.
//
// INTERLEAVE (GEMM1): B-tile n-row r maps to W_hg row (r even: nb + r/2
// hidden; r odd: 512 + nb + r/2 gate) so accumulator col pairs are
// (hidden, gate) of the same channel.
// ---------------------------------------------------------------------------
#define ROWB    144
#define ARR_B   (128*ROWB)     // 18432
#define STG_B   (3*ARR_B)      // 55296
#define SMEM_BYTES (2*STG_B)   // 110592

template<bool INTERLEAVE>
__device__ __forceinline__ void gemm_mainloop(const __half* __restrict__ A,
                                              const __half* __restrict__ Bhi,
                                              const __half* __restrict__ Blo,
                                              int m0, int nb, uint32_t sbase,
                                              float acc[4][4][4]) {
    const int tid  = threadIdx.x;
    const int lane = tid & 31;
    const int wid  = tid >> 5;
    const int wm   = (wid >> 2) * 64;   // warp M offset (0/64)
    const int wn   = (wid & 3) * 32;    // warp N offset (0/32/64/96)

#pragma unroll
    for (int mi = 0; mi < 4; mi++)
#pragma unroll
        for (int ni = 0; ni < 4; ni++)
#pragma unroll
            for (int e = 0; e < 4; e++) acc[mi][ni][e] = 0.0f;

    // ---- stage loader: 12 cp.asyncs per thread (A, Bhi, Blo) ----
    auto load_stage = [&](int j, int s) {
        const uint32_t st = sbase + s * STG_B;
        const int k0 = j * 64;
#pragma unroll
        for (int i = 0; i < 4; i++) {          // 1024 16B-chunks per array
            const int idx = tid + i * 256;
            const int r = idx >> 3, c = idx & 7;
            const uint32_t so = (uint32_t)(r * ROWB + c * 16);
            const size_t goa = (size_t)(m0 + r) * 512 + k0 + c * 8;
            CP_ASYNC16(st + so, (const void*)(A + goa));
            int wr;
            if (INTERLEAVE) wr = (r & 1) ? (512 + nb + (r >> 1)) : (nb + (r >> 1));
            else            wr = nb + r;
            const size_t gob = (size_t)wr * 512 + k0 + c * 8;
            CP_ASYNC16(st + ARR_B     + so, (const void*)(Bhi + gob));
            CP_ASYNC16(st + 2*ARR_B   + so, (const void*)(Blo + gob));
        }
        CP_COMMIT();
    };

    load_stage(0, 0);

    for (int j = 0; j < 8; j++) {
        if (j + 1 < 8) { load_stage(j + 1, (j + 1) & 1); CP_WAIT(1); }
        else           { CP_WAIT(0); }
        __syncthreads();

        const uint32_t st = sbase + (j & 1) * STG_B;
#pragma unroll
        for (int s = 0; s < 4; s++) {          // four k16 steps per stage
            // ---- B fragments: 4 n8 tiles, hi+lo ----
            uint32_t bh[4][2], bl[4][2];
#pragma unroll
            for (int p = 0; p < 2; p++) {
                const int nr = wn + p * 16 + (lane & 7) + ((lane & 16) ? 8 : 0);
                const int ko = s * 16 + ((lane & 8) ? 8 : 0);
                const uint32_t ba = st + ARR_B + (uint32_t)(nr * ROWB + ko * 2);
                LDMX4(bh[p*2][0], bh[p*2][1], bh[p*2+1][0], bh[p*2+1][1], ba);
                LDMX4(bl[p*2][0], bl[p*2][1], bl[p*2+1][0], bl[p*2+1][1], ba + ARR_B);
            }
            // ---- A fragments per m-tile + MMAs ----
#pragma unroll
            for (int mi = 0; mi < 4; mi++) {
                const int mr = wm + mi * 16 + (lane & 15);
                const int ko = s * 16 + ((lane & 16) ? 8 : 0);
                const uint32_t aa = st + (uint32_t)(mr * ROWB + ko * 2);
                uint32_t ah[4];
                LDMX4(ah[0], ah[1], ah[2], ah[3], aa);
#pragma unroll
                for (int ni = 0; ni < 4; ni++) {
                    MMA16816(acc[mi][ni][0], acc[mi][ni][1], acc[mi][ni][2], acc[mi][ni][3],
                             ah[0], ah[1], ah[2], ah[3], bh[ni][0], bh[ni][1]);
                    MMA16816(acc[mi][ni][0], acc[mi][ni][1], acc[mi][ni][2], acc[mi][ni][3],
                             ah[0], ah[1], ah[2], ah[3], bl[ni][0], bl[ni][1]);
                }
            }
        }
        __syncthreads();
    }
}

// ---------------------------------------------------------------------------
// GEMM1: hg = x @ W_hg^T, fused lc/lv epilogue AND fused per-chunk scan
// summaries (scan pass1). Each block = 128 m-rows (exactly one (batch,chunk))
// x 64 channels.
// ---------------------------------------------------------------------------
__global__ __launch_bounds__(256, 2)
void gemm1_mma() {
    extern __shared__ __align__(128) char smem[];
    const uint32_t sbase = smem_u32(smem);
    const int m0 = blockIdx.y * 128;
    const int nb = blockIdx.x * 64;

    float acc[4][4][4];
    gemm_mainloop<true>(g_xh, g_whh, g_whl, m0, nb, sbase, acc);

    // Epilogue: compute lc/lv in regs, stage via smem (stride 76 floats).
    float* lcs = (float*)smem;                      // [128][76]
    float* lvs = lcs + 128 * 76;                    // [128][76]
    float* segA  = (float*)(smem + 77824);          // [4][64]
    float* segLV = segA + 256;                      // [4][64]
    const int tid = threadIdx.x, lane = tid & 31, wid = tid >> 5;
    const int wm = (wid >> 2) * 64;
    const int wn = (wid & 3) * 32;

#pragma unroll
    for (int mi = 0; mi < 4; mi++) {
#pragma unroll
        for (int ni = 0; ni < 4; ni++) {
            const int j  = (wn >> 1) + ni * 4 + (lane & 3);   // channel 0..63
            const int r0 = wm + mi * 16 + (lane >> 2);
#pragma unroll
            for (int e = 0; e < 2; e++) {
                const int r = r0 + e * 8;
                const float hv = acc[mi][ni][2*e];
                const float gv = acc[mi][ni][2*e + 1];
                const float lgv = (hv >= 0.0f) ? __logf(hv + 0.5f) : -sp_f(-hv);
                lcs[r * 76 + j] = -sp_f(gv);
                lvs[r * 76 + j] = lgv - sp_f(-gv);
            }
        }
    }
    __syncthreads();

    // Coalesced float4 stores of lc/lv
    for (int idx = tid; idx < 2048; idx += 256) {
        const int r = idx >> 4, q = idx & 15;
        const size_t go = (size_t)(m0 + r) * HID + nb + q * 4;
        *(float4*)(g_lc + go) = *(float4*)&lcs[r * 76 + q * 4];
        *(float4*)(g_lv + go) = *(float4*)&lvs[r * 76 + q * 4];
    }

    // Fused scan pass1: per-chunk (A, LV). 4 segments of 32 rows per channel.
    {
        const int j = tid & 63, seg = tid >> 6;
        float Acc = 0.0f, LV = -1e30f;
        for (int r = seg * 32; r < seg * 32 + 32; r++) {
            const float lc = lcs[r * 76 + j];
            const float lv = lvs[r * 76 + j];
            LV = lae(lc + LV, lv);
            Acc += lc;
        }
        segA [seg * 64 + j] = Acc;
        segLV[seg * 64 + j] = LV;
    }
    __syncthreads();
    if (tid < 64) {
        float Acc = segA[tid], LV = segLV[tid];
        for (int seg = 1; seg < 4; seg++) {
            const float A2  = segA [seg * 64 + tid];
            const float LV2 = segLV[seg * 64 + tid];
            LV = lae(LV + A2, LV2);    // compose: seg applied after prefix
            Acc += A2;
        }
        const int b = m0 / SEQ, c = (m0 % SEQ) / CHUNK;
        const size_t si = ((size_t)(b * NCH + c)) * HID + nb + tid;
        g_A[si]   = Acc;
        g_LVc[si] = LV;
    }
}

// ---------------------------------------------------------------------------
// GEMM2: out = h @ W_out^T. Grid: (OUTD/128, MROWS/128). Direct f32x2 stores.
// ---------------------------------------------------------------------------
__global__ __launch_bounds__(256, 2)
void gemm2_mma(float* __restrict__ out) {
    extern __shared__ __align__(128) char smem[];
    const uint32_t sbase = smem_u32(smem);
    const int m0 = blockIdx.y * 128;
    const int nb = blockIdx.x * 128;

    float acc[4][4][4];
    gemm_mainloop<false>(g_hh, g_woh, g_wol, m0, nb, sbase, acc);

    const int tid = threadIdx.x, lane = tid & 31, wid = tid >> 5;
    const int wm = (wid >> 2) * 64;
    const int wn = (wid & 3) * 32;

#pragma unroll
    for (int mi = 0; mi < 4; mi++) {
#pragma unroll
        for (int ni = 0; ni < 4; ni++) {
            const int col = nb + wn + ni * 8 + (lane & 3) * 2;
            const int r0  = m0 + wm + mi * 16 + (lane >> 2);
            *(float2*)(out + (size_t)r0 * OUTD + col)
                = make_float2(acc[mi][ni][0], acc[mi][ni][1]);
            *(float2*)(out + (size_t)(r0 + 8) * OUTD + col)
                = make_float2(acc[mi][ni][2], acc[mi][ni][3]);
        }
    }
}

// ---------------------------------------------------------------------------
// Chunked log-space scan (pass1 fused into gemm1 epilogue)
// ---------------------------------------------------------------------------
__global__ __launch_bounds__(512) void scan_pass2() {
    const int b = blockIdx.x, h = threadIdx.x;
    float run = -1e30f;
    for (int c = 0; c < NCH; c++) {
        const size_t si = ((size_t)(b * NCH + c)) * HID + h;
        g_hin[si] = run;
        run = lae(g_A[si] + run, g_LVc[si]);
    }
}

__global__ __launch_bounds__(512) void scan_pass3(float* __restrict__ out_hn) {
    const int b = blockIdx.y, c = blockIdx.x, h = threadIdx.x;
    const size_t si = ((size_t)(b * NCH + c)) * HID + h;
    float lh = g_hin[si];
    size_t base = ((size_t)(b * SEQ + c * CHUNK)) * HID + h;
    float hv = 0.0f;
    for (int t = 0; t < CHUNK; t++) {
        lh = lae(g_lc[base] + lh, g_lv[base]);
        hv = __expf(lh);
        g_hh[base] = __float2half_rn(hv);
        base += HID;
    }
    if (c == NCH - 1)
        out_hn[b * HID + h] = hv;
}

// ---------------------------------------------------------------------------
// Launch. Inputs: x f32 (8,8192,512) | is_init bool(8) | W_hg f32 (1024,512)
// | W_out f32 (512,512). Output: out f32 (B,S,O) ++ h_n f32 (B,1,H).
// ---------------------------------------------------------------------------
extern "C" void kernel_launch(void* const* d_in, const int* in_sizes, int n_in,
                              void* d_out, int out_size) {
    (void)in_sizes; (void)n_in; (void)out_size;
    const float* x    = (const float*)d_in[0];
    const float* Whg  = (const float*)d_in[2];
    const float* Wout = (const float*)d_in[3];
    float* out    = (float*)d_out;
    float* out_hn = out + (size_t)MROWS * OUTD;

    cudaFuncSetAttribute((const void*)gemm1_mma,
                         cudaFuncAttributeMaxDynamicSharedMemorySize, SMEM_BYTES);
    cudaFuncSetAttribute((const void*)gemm2_mma,
                         cudaFuncAttributeMaxDynamicSharedMemorySize, SMEM_BYTES);

    __half *xh, *whh, *whl, *woh, *wol;
    cudaGetSymbolAddress((void**)&xh,  g_xh);
    cudaGetSymbolAddress((void**)&whh, g_whh);
    cudaGetSymbolAddress((void**)&whl, g_whl);
    cudaGetSymbolAddress((void**)&woh, g_woh);
    cudaGetSymbolAddress((void**)&wol, g_wol);

    // fp16 conversion prepass (x: single; weights: hi/lo split)
    cvt_half <<<(MROWS * (size_t)DIM) / 4 / 256, 256>>>(x, xh);
    cvt_split<<<(2 * HID * (size_t)DIM) / 4 / 256, 256>>>(Whg, whh, whl);
    cvt_split<<<(OUTD * (size_t)HID) / 4 / 256, 256>>>(Wout, woh, wol);

    // GEMM1 (fp16 2-product, kc=64) with fused lc/lv + pass1 epilogue
    gemm1_mma<<<dim3(HID / 64, MROWS / 128), 256, SMEM_BYTES>>>();

    // scan (pass1 fused into gemm1)
    scan_pass2<<<BATCH, HID>>>();
    scan_pass3<<<dim3(NCH, BATCH), HID>>>(out_hn);

    // GEMM2 (fp16 2-product, kc=64)
    gemm2_mma<<<dim3(OUTD / 128, MROWS / 128), 256, SMEM_BYTES>>>(out);
}

// round 9
// speedup vs baseline: 2.0791x; 1.3320x over previous
#include <cuda_runtime.h>
#include <cuda_fp16.h>
#include <cstdint>
#include <math.h>

// Problem dimensions (fixed by the reference)
#define BATCH 8
#define SEQ   8192
#define DIM   512
#define HID   512
#define OUTD  512
#define MROWS (BATCH*SEQ)      // 65536
#define CHUNK 128
#define NCH   (SEQ/CHUNK)      // 64

// ---------------------------------------------------------------------------
// Device scratch (no runtime allocation allowed)
// ---------------------------------------------------------------------------
static __device__ float g_lc[(size_t)MROWS*HID];        // log_coeffs
static __device__ float g_lv[(size_t)MROWS*HID];        // log_values
static __device__ float g_A  [(size_t)BATCH*NCH*HID];
static __device__ float g_LVc[(size_t)BATCH*NCH*HID];
static __device__ float g_hin[(size_t)BATCH*NCH*HID];
static __device__ __half g_xh [(size_t)MROWS*DIM];      // x     (fp16)
static __device__ __half g_hh [(size_t)MROWS*HID];      // h     (fp16)
static __device__ __half g_wh [(size_t)2*HID*DIM];      // W_hg  (fp16)
static __device__ __half g_wo [(size_t)OUTD*HID];       // W_out (fp16)

// ---------------------------------------------------------------------------
// PTX helpers (sm_80+ only; no 'a'-suffix features)
// ---------------------------------------------------------------------------
__device__ __forceinline__ uint32_t smem_u32(const void* p) {
    uint32_t a;
    asm("{ .reg .u64 t; cvta.to.shared.u64 t, %1; cvt.u32.u64 %0, t; }" : "=r"(a) : "l"(p));
    return a;
}

#define CP_ASYNC16(dst, src) \
    asm volatile("cp.async.cg.shared.global [%0], [%1], 16;" :: "r"(dst), "l"(src))
#define CP_COMMIT() asm volatile("cp.async.commit_group;" ::: "memory")
#define CP_WAIT(N)  asm volatile("cp.async.wait_group %0;" :: "n"(N) : "memory")

#define LDMX4(r0, r1, r2, r3, a) \
    asm volatile("ldmatrix.sync.aligned.m8n8.x4.shared.b16 {%0,%1,%2,%3}, [%4];" \
        : "=r"(r0), "=r"(r1), "=r"(r2), "=r"(r3) : "r"(a))

// fp16 MMA, fp32 accumulate
#define MMA16816(c0, c1, c2, c3, a0, a1, a2, a3, b0, b1) \
    asm volatile("mma.sync.aligned.m16n8k16.row.col.f32.f16.f16.f32 " \
        "{%0,%1,%2,%3}, {%4,%5,%6,%7}, {%8,%9}, {%0,%1,%2,%3};" \
        : "+f"(c0), "+f"(c1), "+f"(c2), "+f"(c3) \
        : "r"(a0), "r"(a1), "r"(a2), "r"(a3), "r"(b0), "r"(b1))

// ---------------------------------------------------------------------------
// Math helpers
// ---------------------------------------------------------------------------
__device__ __forceinline__ float sp_f(float x) {
    return fmaxf(x, 0.0f) + log1pf(__expf(-fabsf(x)));
}
__device__ __forceinline__ float lae(float a, float b) {
    float m = fmaxf(a, b);
    return m + log1pf(__expf(-fabsf(a - b)));
}

// ---------------------------------------------------------------------------
// fp32 -> fp16 conversion
// ---------------------------------------------------------------------------
__global__ __launch_bounds__(256) void cvt_half(const float* __restrict__ src,
                                                __half* __restrict__ dst) {
    const size_t i = (size_t)blockIdx.x * blockDim.x + threadIdx.x;
    float4 v = ((const float4*)src)[i];
    ((__half2*)dst)[2*i]   = __floats2half2_rn(v.x, v.y);
    ((__half2*)dst)[2*i+1] = __floats2half2_rn(v.z, v.w);
}

// ---------------------------------------------------------------------------
// mma.sync GEMM mainloop. Block 128Mx128N, 256 threads (8 warps, warp tile
// 64x32), K=512, kc=64, THREE-stage cp.async pipeline, 2 CTAs/SM.
// Single fp16 product: acc += A*B (fp32 accumulate).
//
// SMEM stage layout (bytes from stage base), row stride 144B (64 fp16 data
// + 16B pad; conflict-free for cp.async stores and ldmatrix reads):
//   A [0,18432)  B [18432,36864)
// Stage = 36864B, 3 stages = 110592B; 2 CTAs/SM = 221184B < 227KB.
//
// INTERLEAVE (GEMM1): B-tile n-row r maps to W_hg row (r even: nb + r/2
// hidden; r odd: 512 + nb + r/2 gate) so accumulator col pairs are
// (hidden, gate) of the same channel.
// ---------------------------------------------------------------------------
#define ROWB    144
#define ARR_B   (128*ROWB)     // 18432
#define STG_B   (2*ARR_B)      // 36864
#define SMEM_BYTES (3*STG_B)   // 110592

template<bool INTERLEAVE>
__device__ __forceinline__ void gemm_mainloop(const __half* __restrict__ A,
                                              const __half* __restrict__ B,
                                              int m0, int nb, uint32_t sbase,
                                              float acc[4][4][4]) {
    const int tid  = threadIdx.x;
    const int lane = tid & 31;
    const int wid  = tid >> 5;
    const int wm   = (wid >> 2) * 64;   // warp M offset (0/64)
    const int wn   = (wid & 3) * 32;    // warp N offset (0/32/64/96)

#pragma unroll
    for (int mi = 0; mi < 4; mi++)
#pragma unroll
        for (int ni = 0; ni < 4; ni++)
#pragma unroll
            for (int e = 0; e < 4; e++) acc[mi][ni][e] = 0.0f;

    // ---- stage loader: 8 cp.asyncs per thread (A, B) ----
    auto load_stage = [&](int j, int s) {
        const uint32_t st = sbase + s * STG_B;
        const int k0 = j * 64;
#pragma unroll
        for (int i = 0; i < 4; i++) {          // 1024 16B-chunks per array
            const int idx = tid + i * 256;
            const int r = idx >> 3, c = idx & 7;
            const uint32_t so = (uint32_t)(r * ROWB + c * 16);
            const size_t goa = (size_t)(m0 + r) * 512 + k0 + c * 8;
            CP_ASYNC16(st + so, (const void*)(A + goa));
            int wr;
            if (INTERLEAVE) wr = (r & 1) ? (512 + nb + (r >> 1)) : (nb + (r >> 1));
            else            wr = nb + r;
            const size_t gob = (size_t)wr * 512 + k0 + c * 8;
            CP_ASYNC16(st + ARR_B + so, (const void*)(B + gob));
        }
        CP_COMMIT();
    };

    load_stage(0, 0);
    load_stage(1, 1);

    for (int j = 0; j < 8; j++) {
        if (j < 7) { CP_WAIT(1); } else { CP_WAIT(0); }
        __syncthreads();            // all warps done with stage (j+2)%3's old data
        if (j + 2 < 8) load_stage(j + 2, (j + 2) % 3);

        const uint32_t st = sbase + (j % 3) * STG_B;
#pragma unroll
        for (int s = 0; s < 4; s++) {          // four k16 steps per stage
            // ---- B fragments: 4 n8 tiles ----
            uint32_t bh[4][2];
#pragma unroll
            for (int p = 0; p < 2; p++) {
                const int nr = wn + p * 16 + (lane & 7) + ((lane & 16) ? 8 : 0);
                const int ko = s * 16 + ((lane & 8) ? 8 : 0);
                const uint32_t ba = st + ARR_B + (uint32_t)(nr * ROWB + ko * 2);
                LDMX4(bh[p*2][0], bh[p*2][1], bh[p*2+1][0], bh[p*2+1][1], ba);
            }
            // ---- A fragments per m-tile + MMAs ----
#pragma unroll
            for (int mi = 0; mi < 4; mi++) {
                const int mr = wm + mi * 16 + (lane & 15);
                const int ko = s * 16 + ((lane & 16) ? 8 : 0);
                const uint32_t aa = st + (uint32_t)(mr * ROWB + ko * 2);
                uint32_t ah[4];
                LDMX4(ah[0], ah[1], ah[2], ah[3], aa);
#pragma unroll
                for (int ni = 0; ni < 4; ni++) {
                    MMA16816(acc[mi][ni][0], acc[mi][ni][1], acc[mi][ni][2], acc[mi][ni][3],
                             ah[0], ah[1], ah[2], ah[3], bh[ni][0], bh[ni][1]);
                }
            }
        }
    }
    __syncthreads();
}

// ---------------------------------------------------------------------------
// GEMM1: hg = x @ W_hg^T, fused lc/lv epilogue AND fused per-chunk scan
// summaries (scan pass1). Each block = 128 m-rows (exactly one (batch,chunk))
// x 64 channels.
// ---------------------------------------------------------------------------
__global__ __launch_bounds__(256, 2)
void gemm1_mma() {
    extern __shared__ __align__(128) char smem[];
    const uint32_t sbase = smem_u32(smem);
    const int m0 = blockIdx.y * 128;
    const int nb = blockIdx.x * 64;

    float acc[4][4][4];
    gemm_mainloop<true>(g_xh, g_wh, m0, nb, sbase, acc);

    // Epilogue: compute lc/lv in regs, stage via smem (stride 76 floats).
    float* lcs = (float*)smem;                      // [128][76]
    float* lvs = lcs + 128 * 76;                    // [128][76]
    float* segA  = (float*)(smem + 77824);          // [4][64]
    float* segLV = segA + 256;                      // [4][64]
    const int tid = threadIdx.x, lane = tid & 31, wid = tid >> 5;
    const int wm = (wid >> 2) * 64;
    const int wn = (wid & 3) * 32;

#pragma unroll
    for (int mi = 0; mi < 4; mi++) {
#pragma unroll
        for (int ni = 0; ni < 4; ni++) {
            const int j  = (wn >> 1) + ni * 4 + (lane & 3);   // channel 0..63
            const int r0 = wm + mi * 16 + (lane >> 2);
#pragma unroll
            for (int e = 0; e < 2; e++) {
                const int r = r0 + e * 8;
                const float hv = acc[mi][ni][2*e];
                const float gv = acc[mi][ni][2*e + 1];
                const float lgv = (hv >= 0.0f) ? __logf(hv + 0.5f) : -sp_f(-hv);
                lcs[r * 76 + j] = -sp_f(gv);
                lvs[r * 76 + j] = lgv - sp_f(-gv);
            }
        }
    }
    __syncthreads();

    // Coalesced float4 stores of lc/lv
    for (int idx = tid; idx < 2048; idx += 256) {
        const int r = idx >> 4, q = idx & 15;
        const size_t go = (size_t)(m0 + r) * HID + nb + q * 4;
        *(float4*)(g_lc + go) = *(float4*)&lcs[r * 76 + q * 4];
        *(float4*)(g_lv + go) = *(float4*)&lvs[r * 76 + q * 4];
    }

    // Fused scan pass1: per-chunk (A, LV). 4 segments of 32 rows per channel.
    {
        const int j = tid & 63, seg = tid >> 6;
        float Acc = 0.0f, LV = -1e30f;
        for (int r = seg * 32; r < seg * 32 + 32; r++) {
            const float lc = lcs[r * 76 + j];
            const float lv = lvs[r * 76 + j];
            LV = lae(lc + LV, lv);
            Acc += lc;
        }
        segA [seg * 64 + j] = Acc;
        segLV[seg * 64 + j] = LV;
    }
    __syncthreads();
    if (tid < 64) {
        float Acc = segA[tid], LV = segLV[tid];
        for (int seg = 1; seg < 4; seg++) {
            const float A2  = segA [seg * 64 + tid];
            const float LV2 = segLV[seg * 64 + tid];
            LV = lae(LV + A2, LV2);    // compose: seg applied after prefix
            Acc += A2;
        }
        const int b = m0 / SEQ, c = (m0 % SEQ) / CHUNK;
        const size_t si = ((size_t)(b * NCH + c)) * HID + nb + tid;
        g_A[si]   = Acc;
        g_LVc[si] = LV;
    }
}

// ---------------------------------------------------------------------------
// GEMM2: out = h @ W_out^T. Grid: (OUTD/128, MROWS/128). Direct f32x2 stores.
// ---------------------------------------------------------------------------
__global__ __launch_bounds__(256, 2)
void gemm2_mma(float* __restrict__ out) {
    extern __shared__ __align__(128) char smem[];
    const uint32_t sbase = smem_u32(smem);
    const int m0 = blockIdx.y * 128;
    const int nb = blockIdx.x * 128;

    float acc[4][4][4];
    gemm_mainloop<false>(g_hh, g_wo, m0, nb, sbase, acc);

    const int tid = threadIdx.x, lane = tid & 31, wid = tid >> 5;
    const int wm = (wid >> 2) * 64;
    const int wn = (wid & 3) * 32;

#pragma unroll
    for (int mi = 0; mi < 4; mi++) {
#pragma unroll
        for (int ni = 0; ni < 4; ni++) {
            const int col = nb + wn + ni * 8 + (lane & 3) * 2;
            const int r0  = m0 + wm + mi * 16 + (lane >> 2);
            *(float2*)(out + (size_t)r0 * OUTD + col)
                = make_float2(acc[mi][ni][0], acc[mi][ni][1]);
            *(float2*)(out + (size_t)(r0 + 8) * OUTD + col)
                = make_float2(acc[mi][ni][2], acc[mi][ni][3]);
        }
    }
}

// ---------------------------------------------------------------------------
// Chunked log-space scan (pass1 fused into gemm1 epilogue)
// ---------------------------------------------------------------------------
__global__ __launch_bounds__(512) void scan_pass2() {
    const int b = blockIdx.x, h = threadIdx.x;
    float run = -1e30f;
    for (int c = 0; c < NCH; c++) {
        const size_t si = ((size_t)(b * NCH + c)) * HID + h;
        g_hin[si] = run;
        run = lae(g_A[si] + run, g_LVc[si]);
    }
}

__global__ __launch_bounds__(512) void scan_pass3(float* __restrict__ out_hn) {
    const int b = blockIdx.y, c = blockIdx.x, h = threadIdx.x;
    const size_t si = ((size_t)(b * NCH + c)) * HID + h;
    float lh = g_hin[si];
    size_t base = ((size_t)(b * SEQ + c * CHUNK)) * HID + h;
    float hv = 0.0f;
    for (int t = 0; t < CHUNK; t++) {
        lh = lae(g_lc[base] + lh, g_lv[base]);
        hv = __expf(lh);
        g_hh[base] = __float2half_rn(hv);
        base += HID;
    }
    if (c == NCH - 1)
        out_hn[b * HID + h] = hv;
}

// ---------------------------------------------------------------------------
// Launch. Inputs: x f32 (8,8192,512) | is_init bool(8) | W_hg f32 (1024,512)
// | W_out f32 (512,512). Output: out f32 (B,S,O) ++ h_n f32 (B,1,H).
// ---------------------------------------------------------------------------
extern "C" void kernel_launch(void* const* d_in, const int* in_sizes, int n_in,
                              void* d_out, int out_size) {
    (void)in_sizes; (void)n_in; (void)out_size;
    const float* x    = (const float*)d_in[0];
    const float* Whg  = (const float*)d_in[2];
    const float* Wout = (const float*)d_in[3];
    float* out    = (float*)d_out;
    float* out_hn = out + (size_t)MROWS * OUTD;

    cudaFuncSetAttribute((const void*)gemm1_mma,
                         cudaFuncAttributeMaxDynamicSharedMemorySize, SMEM_BYTES);
    cudaFuncSetAttribute((const void*)gemm2_mma,
                         cudaFuncAttributeMaxDynamicSharedMemorySize, SMEM_BYTES);

    __half *xh, *wh, *wo;
    cudaGetSymbolAddress((void**)&xh, g_xh);
    cudaGetSymbolAddress((void**)&wh, g_wh);
    cudaGetSymbolAddress((void**)&wo, g_wo);

    // fp16 conversion prepass (all single fp16)
    cvt_half<<<(MROWS * (size_t)DIM) / 4 / 256, 256>>>(x, xh);
    cvt_half<<<(2 * HID * (size_t)DIM) / 4 / 256, 256>>>(Whg, wh);
    cvt_half<<<(OUTD * (size_t)HID) / 4 / 256, 256>>>(Wout, wo);

    // GEMM1 (fp16 single-product, kc=64, 3-stage) + fused lc/lv + pass1
    gemm1_mma<<<dim3(HID / 64, MROWS / 128), 256, SMEM_BYTES>>>();

    // scan (pass1 fused into gemm1)
    scan_pass2<<<BATCH, HID>>>();
    scan_pass3<<<dim3(NCH, BATCH), HID>>>(out_hn);

    // GEMM2 (fp16 single-product, kc=64, 3-stage)
    gemm2_mma<<<dim3(OUTD / 128, MROWS / 128), 256, SMEM_BYTES>>>(out);
}

// round 10
// speedup vs baseline: 2.4618x; 1.1841x over previous
#include <cuda_runtime.h>
#include <cuda_fp16.h>
#include <cstdint>
#include <math.h>

// Problem dimensions (fixed by the reference)
#define BATCH 8
#define SEQ   8192
#define DIM   512
#define HID   512
#define OUTD  512
#define MROWS (BATCH*SEQ)      // 65536
#define CHUNK 128
#define NCH   (SEQ/CHUNK)      // 64

// ---------------------------------------------------------------------------
// Device scratch (no runtime allocation allowed)
// ---------------------------------------------------------------------------
static __device__ float g_lc[(size_t)MROWS*HID];        // log_coeffs
static __device__ float g_lv[(size_t)MROWS*HID];        // log_values
static __device__ float g_A  [(size_t)BATCH*NCH*HID];
static __device__ float g_LVc[(size_t)BATCH*NCH*HID];
static __device__ float g_hin[(size_t)BATCH*NCH*HID];
static __device__ __half g_xh [(size_t)MROWS*DIM];      // x     (fp16)
static __device__ __half g_hh [(size_t)MROWS*HID];      // h     (fp16)
static __device__ __half g_wh [(size_t)2*HID*DIM];      // W_hg  (fp16)
static __device__ __half g_wo [(size_t)OUTD*HID];       // W_out (fp16)

// ---------------------------------------------------------------------------
// PTX helpers (sm_80+ only; no 'a'-suffix features)
// ---------------------------------------------------------------------------
__device__ __forceinline__ uint32_t smem_u32(const void* p) {
    uint32_t a;
    asm("{ .reg .u64 t; cvta.to.shared.u64 t, %1; cvt.u32.u64 %0, t; }" : "=r"(a) : "l"(p));
    return a;
}

#define CP_ASYNC16(dst, src) \
    asm volatile("cp.async.cg.shared.global [%0], [%1], 16;" :: "r"(dst), "l"(src))
#define CP_COMMIT() asm volatile("cp.async.commit_group;" ::: "memory")
#define CP_WAIT(N)  asm volatile("cp.async.wait_group %0;" :: "n"(N) : "memory")

#define LDMX4(r0, r1, r2, r3, a) \
    asm volatile("ldmatrix.sync.aligned.m8n8.x4.shared.b16 {%0,%1,%2,%3}, [%4];" \
        : "=r"(r0), "=r"(r1), "=r"(r2), "=r"(r3) : "r"(a))

// fp16 MMA, fp32 accumulate
#define MMA16816(c0, c1, c2, c3, a0, a1, a2, a3, b0, b1) \
    asm volatile("mma.sync.aligned.m16n8k16.row.col.f32.f16.f16.f32 " \
        "{%0,%1,%2,%3}, {%4,%5,%6,%7}, {%8,%9}, {%0,%1,%2,%3};" \
        : "+f"(c0), "+f"(c1), "+f"(c2), "+f"(c3) \
        : "r"(a0), "r"(a1), "r"(a2), "r"(a3), "r"(b0), "r"(b1))

// ---------------------------------------------------------------------------
// Math helpers (fast: MUFU-based, no library log1pf)
// softplus(x) = max(x,0) + log(1 + exp(-|x|))
// ---------------------------------------------------------------------------
__device__ __forceinline__ float sp_f(float x) {
    return fmaxf(x, 0.0f) + __logf(1.0f + __expf(-fabsf(x)));
}
__device__ __forceinline__ float lae(float a, float b) {
    float m = fmaxf(a, b);
    return m + __logf(1.0f + __expf(-fabsf(a - b)));
}

// ---------------------------------------------------------------------------
// fp32 -> fp16 conversion
// ---------------------------------------------------------------------------
__global__ __launch_bounds__(256) void cvt_half(const float* __restrict__ src,
                                                __half* __restrict__ dst) {
    const size_t i = (size_t)blockIdx.x * blockDim.x + threadIdx.x;
    float4 v = ((const float4*)src)[i];
    ((__half2*)dst)[2*i]   = __floats2half2_rn(v.x, v.y);
    ((__half2*)dst)[2*i+1] = __floats2half2_rn(v.z, v.w);
}

// ---------------------------------------------------------------------------
// mma.sync GEMM mainloop. Block 128Mx128N, 256 threads (8 warps, warp tile
// 64x32), K=512, kc=64, THREE-stage cp.async pipeline, 2 CTAs/SM.
// Single fp16 product: acc += A*B (fp32 accumulate).
//
// SMEM stage layout (bytes from stage base), row stride 144B:
//   A [0,18432)  B [18432,36864)
// Stage = 36864B, 3 stages = 110592B; 2 CTAs/SM = 221184B < 227KB.
//
// INTERLEAVE (GEMM1): B-tile n-row r maps to W_hg row (r even: nb + r/2
// hidden; r odd: 512 + nb + r/2 gate).
// ---------------------------------------------------------------------------
#define ROWB    144
#define ARR_B   (128*ROWB)     // 18432
#define STG_B   (2*ARR_B)      // 36864
#define SMEM_BYTES (3*STG_B)   // 110592

template<bool INTERLEAVE>
__device__ __forceinline__ void gemm_mainloop(const __half* __restrict__ A,
                                              const __half* __restrict__ B,
                                              int m0, int nb, uint32_t sbase,
                                              float acc[4][4][4]) {
    const int tid  = threadIdx.x;
    const int lane = tid & 31;
    const int wid  = tid >> 5;
    const int wm   = (wid >> 2) * 64;   // warp M offset (0/64)
    const int wn   = (wid & 3) * 32;    // warp N offset (0/32/64/96)

#pragma unroll
    for (int mi = 0; mi < 4; mi++)
#pragma unroll
        for (int ni = 0; ni < 4; ni++)
#pragma unroll
            for (int e = 0; e < 4; e++) acc[mi][ni][e] = 0.0f;

    // Hoisted, lane-invariant ldmatrix offsets (per-step address = st + off + s*32)
    uint32_t a_off[4], b_off[2];
#pragma unroll
    for (int mi = 0; mi < 4; mi++)
        a_off[mi] = (uint32_t)((wm + mi * 16 + (lane & 15)) * ROWB
                               + ((lane & 16) ? 16 : 0));
#pragma unroll
    for (int p = 0; p < 2; p++)
        b_off[p] = (uint32_t)(ARR_B
                   + (wn + p * 16 + (lane & 7) + ((lane & 16) ? 8 : 0)) * ROWB
                   + ((lane & 8) ? 16 : 0));

    // ---- stage loader: 8 cp.asyncs per thread (A, B) ----
    auto load_stage = [&](int j, int s) {
        const uint32_t st = sbase + s * STG_B;
        const int k0 = j * 64;
#pragma unroll
        for (int i = 0; i < 4; i++) {          // 1024 16B-chunks per array
            const int idx = tid + i * 256;
            const int r = idx >> 3, c = idx & 7;
            const uint32_t so = (uint32_t)(r * ROWB + c * 16);
            const size_t goa = (size_t)(m0 + r) * 512 + k0 + c * 8;
            CP_ASYNC16(st + so, (const void*)(A + goa));
            int wr;
            if (INTERLEAVE) wr = (r & 1) ? (512 + nb + (r >> 1)) : (nb + (r >> 1));
            else            wr = nb + r;
            const size_t gob = (size_t)wr * 512 + k0 + c * 8;
            CP_ASYNC16(st + ARR_B + so, (const void*)(B + gob));
        }
        CP_COMMIT();
    };

    load_stage(0, 0);
    load_stage(1, 1);

    for (int j = 0; j < 8; j++) {
        if (j < 7) { CP_WAIT(1); } else { CP_WAIT(0); }
        __syncthreads();            // all warps done with stage (j+2)%3's old data
        if (j + 2 < 8) load_stage(j + 2, (j + 2) % 3);

        const uint32_t st = sbase + (j % 3) * STG_B;
#pragma unroll
        for (int s = 0; s < 4; s++) {          // four k16 steps per stage
            const uint32_t sk = st + (uint32_t)(s * 32);
            // ---- issue ALL fragments first (6 LDSM back-to-back) ----
            uint32_t bh[4][2], ah[4][4];
            LDMX4(bh[0][0], bh[0][1], bh[1][0], bh[1][1], sk + b_off[0]);
            LDMX4(bh[2][0], bh[2][1], bh[3][0], bh[3][1], sk + b_off[1]);
#pragma unroll
            for (int mi = 0; mi < 4; mi++)
                LDMX4(ah[mi][0], ah[mi][1], ah[mi][2], ah[mi][3], sk + a_off[mi]);
            // ---- then 16 MMAs ----
#pragma unroll
            for (int mi = 0; mi < 4; mi++)
#pragma unroll
                for (int ni = 0; ni < 4; ni++)
                    MMA16816(acc[mi][ni][0], acc[mi][ni][1], acc[mi][ni][2], acc[mi][ni][3],
                             ah[mi][0], ah[mi][1], ah[mi][2], ah[mi][3],
                             bh[ni][0], bh[ni][1]);
        }
    }
    __syncthreads();
}

// ---------------------------------------------------------------------------
// GEMM1: hg = x @ W_hg^T, fused lc/lv epilogue AND fused per-chunk scan
// summaries (scan pass1). Each block = 128 m-rows (one (batch,chunk)) x 64 ch.
// ---------------------------------------------------------------------------
__global__ __launch_bounds__(256, 2)
void gemm1_mma() {
    extern __shared__ __align__(128) char smem[];
    const uint32_t sbase = smem_u32(smem);
    const int m0 = blockIdx.y * 128;
    const int nb = blockIdx.x * 64;

    float acc[4][4][4];
    gemm_mainloop<true>(g_xh, g_wh, m0, nb, sbase, acc);

    // Epilogue: compute lc/lv in regs, stage via smem (stride 76 floats).
    float* lcs = (float*)smem;                      // [128][76]
    float* lvs = lcs + 128 * 76;                    // [128][76]
    float* segA  = (float*)(smem + 77824);          // [4][64]
    float* segLV = segA + 256;                      // [4][64]
    const int tid = threadIdx.x, lane = tid & 31, wid = tid >> 5;
    const int wm = (wid >> 2) * 64;
    const int wn = (wid & 3) * 32;

#pragma unroll
    for (int mi = 0; mi < 4; mi++) {
#pragma unroll
        for (int ni = 0; ni < 4; ni++) {
            const int j  = (wn >> 1) + ni * 4 + (lane & 3);   // channel 0..63
            const int r0 = wm + mi * 16 + (lane >> 2);
#pragma unroll
            for (int e = 0; e < 2; e++) {
                const int r = r0 + e * 8;
                const float hv = acc[mi][ni][2*e];
                const float gv = acc[mi][ni][2*e + 1];
                const float lgv = (hv >= 0.0f) ? __logf(hv + 0.5f) : -sp_f(-hv);
                lcs[r * 76 + j] = -sp_f(gv);
                lvs[r * 76 + j] = lgv - sp_f(-gv);
            }
        }
    }
    __syncthreads();

    // Coalesced float4 stores of lc/lv
    for (int idx = tid; idx < 2048; idx += 256) {
        const int r = idx >> 4, q = idx & 15;
        const size_t go = (size_t)(m0 + r) * HID + nb + q * 4;
        *(float4*)(g_lc + go) = *(float4*)&lcs[r * 76 + q * 4];
        *(float4*)(g_lv + go) = *(float4*)&lvs[r * 76 + q * 4];
    }

    // Fused scan pass1: per-chunk (A, LV). 4 segments of 32 rows per channel.
    {
        const int j = tid & 63, seg = tid >> 6;
        float Acc = 0.0f, LV = -1e30f;
        for (int r = seg * 32; r < seg * 32 + 32; r++) {
            const float lc = lcs[r * 76 + j];
            const float lv = lvs[r * 76 + j];
            LV = lae(lc + LV, lv);
            Acc += lc;
        }
        segA [seg * 64 + j] = Acc;
        segLV[seg * 64 + j] = LV;
    }
    __syncthreads();
    if (tid < 64) {
        float Acc = segA[tid], LV = segLV[tid];
        for (int seg = 1; seg < 4; seg++) {
            const float A2  = segA [seg * 64 + tid];
            const float LV2 = segLV[seg * 64 + tid];
            LV = lae(LV + A2, LV2);    // compose: seg applied after prefix
            Acc += A2;
        }
        const int b = m0 / SEQ, c = (m0 % SEQ) / CHUNK;
        const size_t si = ((size_t)(b * NCH + c)) * HID + nb + tid;
        g_A[si]   = Acc;
        g_LVc[si] = LV;
    }
}

// ---------------------------------------------------------------------------
// GEMM2: out = h @ W_out^T. Grid: (OUTD/128, MROWS/128). Direct f32x2 stores.
// ---------------------------------------------------------------------------
__global__ __launch_bounds__(256, 2)
void gemm2_mma(float* __restrict__ out) {
    extern __shared__ __align__(128) char smem[];
    const uint32_t sbase = smem_u32(smem);
    const int m0 = blockIdx.y * 128;
    const int nb = blockIdx.x * 128;

    float acc[4][4][4];
    gemm_mainloop<false>(g_hh, g_wo, m0, nb, sbase, acc);

    const int tid = threadIdx.x, lane = tid & 31, wid = tid >> 5;
    const int wm = (wid >> 2) * 64;
    const int wn = (wid & 3) * 32;

#pragma unroll
    for (int mi = 0; mi < 4; mi++) {
#pragma unroll
        for (int ni = 0; ni < 4; ni++) {
            const int col = nb + wn + ni * 8 + (lane & 3) * 2;
            const int r0  = m0 + wm + mi * 16 + (lane >> 2);
            *(float2*)(out + (size_t)r0 * OUTD + col)
                = make_float2(acc[mi][ni][0], acc[mi][ni][1]);
            *(float2*)(out + (size_t)(r0 + 8) * OUTD + col)
                = make_float2(acc[mi][ni][2], acc[mi][ni][3]);
        }
    }
}

// ---------------------------------------------------------------------------
// Chunked log-space scan (pass1 fused into gemm1 epilogue)
// ---------------------------------------------------------------------------
__global__ __launch_bounds__(512) void scan_pass2() {
    const int b = blockIdx.x, h = threadIdx.x;
    float run = -1e30f;
    for (int c = 0; c < NCH; c++) {
        const size_t si = ((size_t)(b * NCH + c)) * HID + h;
        g_hin[si] = run;
        run = lae(g_A[si] + run, g_LVc[si]);
    }
}

__global__ __launch_bounds__(512) void scan_pass3(float* __restrict__ out_hn) {
    const int b = blockIdx.y, c = blockIdx.x, h = threadIdx.x;
    const size_t si = ((size_t)(b * NCH + c)) * HID + h;
    float lh = g_hin[si];
    size_t base = ((size_t)(b * SEQ + c * CHUNK)) * HID + h;
    float hv = 0.0f;
    for (int t = 0; t < CHUNK; t++) {
        lh = lae(g_lc[base] + lh, g_lv[base]);
        hv = __expf(lh);
        g_hh[base] = __float2half_rn(hv);
        base += HID;
    }
    if (c == NCH - 1)
        out_hn[b * HID + h] = hv;
}

// ---------------------------------------------------------------------------
// Launch. Inputs: x f32 (8,8192,512) | is_init bool(8) | W_hg f32 (1024,512)
// | W_out f32 (512,512). Output: out f32 (B,S,O) ++ h_n f32 (B,1,H).
// ---------------------------------------------------------------------------
extern "C" void kernel_launch(void* const* d_in, const int* in_sizes, int n_in,
                              void* d_out, int out_size) {
    (void)in_sizes; (void)n_in; (void)out_size;
    const float* x    = (const float*)d_in[0];
    const float* Whg  = (const float*)d_in[2];
    const float* Wout = (const float*)d_in[3];
    float* out    = (float*)d_out;
    float* out_hn = out + (size_t)MROWS * OUTD;

    cudaFuncSetAttribute((const void*)gemm1_mma,
                         cudaFuncAttributeMaxDynamicSharedMemorySize, SMEM_BYTES);
    cudaFuncSetAttribute((const void*)gemm2_mma,
                         cudaFuncAttributeMaxDynamicSharedMemorySize, SMEM_BYTES);

    __half *xh, *wh, *wo;
    cudaGetSymbolAddress((void**)&xh, g_xh);
    cudaGetSymbolAddress((void**)&wh, g_wh);
    cudaGetSymbolAddress((void**)&wo, g_wo);

    // fp16 conversion prepass
    cvt_half<<<(MROWS * (size_t)DIM) / 4 / 256, 256>>>(x, xh);
    cvt_half<<<(2 * HID * (size_t)DIM) / 4 / 256, 256>>>(Whg, wh);
    cvt_half<<<(OUTD * (size_t)HID) / 4 / 256, 256>>>(Wout, wo);

    // GEMM1 (fp16, kc=64, 3-stage) + fused lc/lv + pass1
    gemm1_mma<<<dim3(HID / 64, MROWS / 128), 256, SMEM_BYTES>>>();

    // scan (pass1 fused into gemm1)
    scan_pass2<<<BATCH, HID>>>();
    scan_pass3<<<dim3(NCH, BATCH), HID>>>(out_hn);

    // GEMM2 (fp16, kc=64, 3-stage)
    gemm2_mma<<<dim3(OUTD / 128, MROWS / 128), 256, SMEM_BYTES>>>(out);
}

// round 11
// speedup vs baseline: 2.5650x; 1.0420x over previous
#include <cuda_runtime.h>
#include <cuda_fp16.h>
#include <cstdint>
#include <math.h>

// Problem dimensions (fixed by the reference)
#define BATCH 8
#define SEQ   8192
#define DIM   512
#define HID   512
#define OUTD  512
#define MROWS (BATCH*SEQ)      // 65536
#define CHUNK 128
#define NCH   (SEQ/CHUNK)      // 64

// ---------------------------------------------------------------------------
// Device scratch (no runtime allocation allowed)
// ---------------------------------------------------------------------------
static __device__ __half g_lch[(size_t)MROWS*HID];      // log_coeffs (fp16)
static __device__ __half g_lvh[(size_t)MROWS*HID];      // log_values (fp16)
static __device__ float g_A  [(size_t)BATCH*NCH*HID];   // chunk sum log_coeffs
static __device__ float g_LVc[(size_t)BATCH*NCH*HID];   // chunk log-value
static __device__ __half g_xh [(size_t)MROWS*DIM];      // x     (fp16)
static __device__ __half g_hh [(size_t)MROWS*HID];      // h     (fp16)
static __device__ __half g_wh [(size_t)2*HID*DIM];      // W_hg  (fp16)
static __device__ __half g_wo [(size_t)OUTD*HID];       // W_out (fp16)

// ---------------------------------------------------------------------------
// PTX helpers (sm_80+ only; no 'a'-suffix features)
// ---------------------------------------------------------------------------
__device__ __forceinline__ uint32_t smem_u32(const void* p) {
    uint32_t a;
    asm("{ .reg .u64 t; cvta.to.shared.u64 t, %1; cvt.u32.u64 %0, t; }" : "=r"(a) : "l"(p));
    return a;
}

#define CP_ASYNC16(dst, src) \
    asm volatile("cp.async.cg.shared.global [%0], [%1], 16;" :: "r"(dst), "l"(src))
#define CP_COMMIT() asm volatile("cp.async.commit_group;" ::: "memory")
#define CP_WAIT(N)  asm volatile("cp.async.wait_group %0;" :: "n"(N) : "memory")

#define LDMX4(r0, r1, r2, r3, a) \
    asm volatile("ldmatrix.sync.aligned.m8n8.x4.shared.b16 {%0,%1,%2,%3}, [%4];" \
        : "=r"(r0), "=r"(r1), "=r"(r2), "=r"(r3) : "r"(a))

// fp16 MMA, fp32 accumulate
#define MMA16816(c0, c1, c2, c3, a0, a1, a2, a3, b0, b1) \
    asm volatile("mma.sync.aligned.m16n8k16.row.col.f32.f16.f16.f32 " \
        "{%0,%1,%2,%3}, {%4,%5,%6,%7}, {%8,%9}, {%0,%1,%2,%3};" \
        : "+f"(c0), "+f"(c1), "+f"(c2), "+f"(c3) \
        : "r"(a0), "r"(a1), "r"(a2), "r"(a3), "r"(b0), "r"(b1))

// ---------------------------------------------------------------------------
// Math helpers (fast MUFU path)
// ---------------------------------------------------------------------------
__device__ __forceinline__ float sp_f(float x) {
    return fmaxf(x, 0.0f) + __logf(1.0f + __expf(-fabsf(x)));
}
__device__ __forceinline__ float lae(float a, float b) {
    float m = fmaxf(a, b);
    return m + __logf(1.0f + __expf(-fabsf(a - b)));
}

// ---------------------------------------------------------------------------
// fp32 -> fp16 conversion
// ---------------------------------------------------------------------------
__global__ __launch_bounds__(256) void cvt_half(const float* __restrict__ src,
                                                __half* __restrict__ dst) {
    const size_t i = (size_t)blockIdx.x * blockDim.x + threadIdx.x;
    float4 v = ((const float4*)src)[i];
    ((__half2*)dst)[2*i]   = __floats2half2_rn(v.x, v.y);
    ((__half2*)dst)[2*i+1] = __floats2half2_rn(v.z, v.w);
}

// ---------------------------------------------------------------------------
// mma.sync GEMM mainloop. Block 128Mx128N, 256 threads (8 warps, warp tile
// 64x32), K=512, kc=64, THREE-stage cp.async pipeline, 2 CTAs/SM.
// Single fp16 product: acc += A*B (fp32 accumulate).
// SMEM stage: A [0,18432)  B [18432,36864), row stride 144B.
// INTERLEAVE (GEMM1): B-tile n-row r -> W_hg row (even: hidden, odd: gate).
// ---------------------------------------------------------------------------
#define ROWB    144
#define ARR_B   (128*ROWB)     // 18432
#define STG_B   (2*ARR_B)      // 36864
#define SMEM_BYTES (3*STG_B)   // 110592

template<bool INTERLEAVE>
__device__ __forceinline__ void gemm_mainloop(const __half* __restrict__ A,
                                              const __half* __restrict__ B,
                                              int m0, int nb, uint32_t sbase,
                                              float acc[4][4][4]) {
    const int tid  = threadIdx.x;
    const int lane = tid & 31;
    const int wid  = tid >> 5;
    const int wm   = (wid >> 2) * 64;   // warp M offset (0/64)
    const int wn   = (wid & 3) * 32;    // warp N offset (0/32/64/96)

#pragma unroll
    for (int mi = 0; mi < 4; mi++)
#pragma unroll
        for (int ni = 0; ni < 4; ni++)
#pragma unroll
            for (int e = 0; e < 4; e++) acc[mi][ni][e] = 0.0f;

    // Hoisted, lane-invariant ldmatrix offsets (per-step addr = st + off + s*32)
    uint32_t a_off[4], b_off[2];
#pragma unroll
    for (int mi = 0; mi < 4; mi++)
        a_off[mi] = (uint32_t)((wm + mi * 16 + (lane & 15)) * ROWB
                               + ((lane & 16) ? 16 : 0));
#pragma unroll
    for (int p = 0; p < 2; p++)
        b_off[p] = (uint32_t)(ARR_B
                   + (wn + p * 16 + (lane & 7) + ((lane & 16) ? 8 : 0)) * ROWB
                   + ((lane & 8) ? 16 : 0));

    // ---- stage loader: 8 cp.asyncs per thread (A, B) ----
    auto load_stage = [&](int j, int s) {
        const uint32_t st = sbase + s * STG_B;
        const int k0 = j * 64;
#pragma unroll
        for (int i = 0; i < 4; i++) {          // 1024 16B-chunks per array
            const int idx = tid + i * 256;
            const int r = idx >> 3, c = idx & 7;
            const uint32_t so = (uint32_t)(r * ROWB + c * 16);
            const size_t goa = (size_t)(m0 + r) * 512 + k0 + c * 8;
            CP_ASYNC16(st + so, (const void*)(A + goa));
            int wr;
            if (INTERLEAVE) wr = (r & 1) ? (512 + nb + (r >> 1)) : (nb + (r >> 1));
            else            wr = nb + r;
            const size_t gob = (size_t)wr * 512 + k0 + c * 8;
            CP_ASYNC16(st + ARR_B + so, (const void*)(B + gob));
        }
        CP_COMMIT();
    };

    load_stage(0, 0);
    load_stage(1, 1);

    for (int j = 0; j < 8; j++) {
        if (j < 7) { CP_WAIT(1); } else { CP_WAIT(0); }
        __syncthreads();            // all warps done with stage (j+2)%3's old data
        if (j + 2 < 8) load_stage(j + 2, (j + 2) % 3);

        const uint32_t st = sbase + (j % 3) * STG_B;
#pragma unroll
        for (int s = 0; s < 4; s++) {          // four k16 steps per stage
            const uint32_t sk = st + (uint32_t)(s * 32);
            // ---- issue ALL fragments first (6 LDSM back-to-back) ----
            uint32_t bh[4][2], ah[4][4];
            LDMX4(bh[0][0], bh[0][1], bh[1][0], bh[1][1], sk + b_off[0]);
            LDMX4(bh[2][0], bh[2][1], bh[3][0], bh[3][1], sk + b_off[1]);
#pragma unroll
            for (int mi = 0; mi < 4; mi++)
                LDMX4(ah[mi][0], ah[mi][1], ah[mi][2], ah[mi][3], sk + a_off[mi]);
            // ---- then 16 MMAs ----
#pragma unroll
            for (int mi = 0; mi < 4; mi++)
#pragma unroll
                for (int ni = 0; ni < 4; ni++)
                    MMA16816(acc[mi][ni][0], acc[mi][ni][1], acc[mi][ni][2], acc[mi][ni][3],
                             ah[mi][0], ah[mi][1], ah[mi][2], ah[mi][3],
                             bh[ni][0], bh[ni][1]);
        }
    }
    __syncthreads();
}

// ---------------------------------------------------------------------------
// GEMM1: hg = x @ W_hg^T, fused lc/lv epilogue (fp16 stores) AND fused
// per-chunk scan summaries (pass1). Block = 128 m-rows (one (batch,chunk))
// x 64 channels.
// ---------------------------------------------------------------------------
__global__ __launch_bounds__(256, 2)
void gemm1_mma() {
    extern __shared__ __align__(128) char smem[];
    const uint32_t sbase = smem_u32(smem);
    const int m0 = blockIdx.y * 128;
    const int nb = blockIdx.x * 64;

    float acc[4][4][4];
    gemm_mainloop<true>(g_xh, g_wh, m0, nb, sbase, acc);

    // Epilogue: compute lc/lv in regs, stage fp32 via smem (stride 76 floats).
    float* lcs = (float*)smem;                      // [128][76]
    float* lvs = lcs + 128 * 76;                    // [128][76]
    float* segA  = (float*)(smem + 77824);          // [4][64]
    float* segLV = segA + 256;                      // [4][64]
    const int tid = threadIdx.x, lane = tid & 31, wid = tid >> 5;
    const int wm = (wid >> 2) * 64;
    const int wn = (wid & 3) * 32;

#pragma unroll
    for (int mi = 0; mi < 4; mi++) {
#pragma unroll
        for (int ni = 0; ni < 4; ni++) {
            const int j  = (wn >> 1) + ni * 4 + (lane & 3);   // channel 0..63
            const int r0 = wm + mi * 16 + (lane >> 2);
#pragma unroll
            for (int e = 0; e < 2; e++) {
                const int r = r0 + e * 8;
                const float hv = acc[mi][ni][2*e];
                const float gv = acc[mi][ni][2*e + 1];
                const float lgv = (hv >= 0.0f) ? __logf(hv + 0.5f) : -sp_f(-hv);
                lcs[r * 76 + j] = -sp_f(gv);
                lvs[r * 76 + j] = lgv - sp_f(-gv);
            }
        }
    }
    __syncthreads();

    // Coalesced fp16 stores of lc/lv (4 halves = 8B per store)
    for (int idx = tid; idx < 2048; idx += 256) {
        const int r = idx >> 4, q = idx & 15;
        const size_t go = (size_t)(m0 + r) * HID + nb + q * 4;
        float4 vc = *(float4*)&lcs[r * 76 + q * 4];
        float4 vv = *(float4*)&lvs[r * 76 + q * 4];
        __half2 c2[2] = { __floats2half2_rn(vc.x, vc.y), __floats2half2_rn(vc.z, vc.w) };
        __half2 v2[2] = { __floats2half2_rn(vv.x, vv.y), __floats2half2_rn(vv.z, vv.w) };
        *(uint2*)(g_lch + go) = *(uint2*)c2;
        *(uint2*)(g_lvh + go) = *(uint2*)v2;
    }

    // Fused scan pass1: per-chunk (A, LV). 4 segments of 32 rows per channel.
    {
        const int j = tid & 63, seg = tid >> 6;
        float Acc = 0.0f, LV = -1e30f;
        for (int r = seg * 32; r < seg * 32 + 32; r++) {
            const float lc = lcs[r * 76 + j];
            const float lv = lvs[r * 76 + j];
            LV = lae(lc + LV, lv);
            Acc += lc;
        }
        segA [seg * 64 + j] = Acc;
        segLV[seg * 64 + j] = LV;
    }
    __syncthreads();
    if (tid < 64) {
        float Acc = segA[tid], LV = segLV[tid];
        for (int seg = 1; seg < 4; seg++) {
            const float A2  = segA [seg * 64 + tid];
            const float LV2 = segLV[seg * 64 + tid];
            LV = lae(LV + A2, LV2);    // compose: seg applied after prefix
            Acc += A2;
        }
        const int b = m0 / SEQ, c = (m0 % SEQ) / CHUNK;
        const size_t si = ((size_t)(b * NCH + c)) * HID + nb + tid;
        g_A[si]   = Acc;
        g_LVc[si] = LV;
    }
}

// ---------------------------------------------------------------------------
// GEMM2: out = h @ W_out^T. Grid: (OUTD/128, MROWS/128). Direct f32x2 stores.
// ---------------------------------------------------------------------------
__global__ __launch_bounds__(256, 2)
void gemm2_mma(float* __restrict__ out) {
    extern __shared__ __align__(128) char smem[];
    const uint32_t sbase = smem_u32(smem);
    const int m0 = blockIdx.y * 128;
    const int nb = blockIdx.x * 128;

    float acc[4][4][4];
    gemm_mainloop<false>(g_hh, g_wo, m0, nb, sbase, acc);

    const int tid = threadIdx.x, lane = tid & 31, wid = tid >> 5;
    const int wm = (wid >> 2) * 64;
    const int wn = (wid & 3) * 32;

#pragma unroll
    for (int mi = 0; mi < 4; mi++) {
#pragma unroll
        for (int ni = 0; ni < 4; ni++) {
            const int col = nb + wn + ni * 8 + (lane & 3) * 2;
            const int r0  = m0 + wm + mi * 16 + (lane >> 2);
            *(float2*)(out + (size_t)r0 * OUTD + col)
                = make_float2(acc[mi][ni][0], acc[mi][ni][1]);
            *(float2*)(out + (size_t)(r0 + 8) * OUTD + col)
                = make_float2(acc[mi][ni][2], acc[mi][ni][3]);
        }
    }
}

// ---------------------------------------------------------------------------
// Scan pass3 (pass2 fused): block = one (batch, chunk); 128 threads x 4
// channels. Each block recomputes its inter-chunk prefix from the
// L2-resident g_A/g_LVc (1 MB total), then replays its chunk, emitting
// fp16 h.
// ---------------------------------------------------------------------------
__global__ __launch_bounds__(128) void scan_pass3(float* __restrict__ out_hn) {
    const int b = blockIdx.y, cid = blockIdx.x;
    const int ch = threadIdx.x * 4;

    // Fused pass2: prefix over chunks [0, cid)
    float4 lh = make_float4(-1e30f, -1e30f, -1e30f, -1e30f);
    for (int c = 0; c < cid; c++) {
        const size_t si = ((size_t)(b * NCH + c)) * HID + ch;
        const float4 A4 = *(const float4*)(g_A + si);
        const float4 L4 = *(const float4*)(g_LVc + si);
        lh.x = lae(A4.x + lh.x, L4.x);
        lh.y = lae(A4.y + lh.y, L4.y);
        lh.z = lae(A4.z + lh.z, L4.z);
        lh.w = lae(A4.w + lh.w, L4.w);
    }

    // Chunk replay
    size_t base = ((size_t)(b * SEQ + cid * CHUNK)) * HID + ch;
    float4 hv = make_float4(0.f, 0.f, 0.f, 0.f);
#pragma unroll 4
    for (int t = 0; t < CHUNK; t++) {
        const uint2 pc = *(const uint2*)(g_lch + base);
        const uint2 pv = *(const uint2*)(g_lvh + base);
        const float2 c01 = __half22float2(*(const __half2*)&pc.x);
        const float2 c23 = __half22float2(*(const __half2*)&pc.y);
        const float2 v01 = __half22float2(*(const __half2*)&pv.x);
        const float2 v23 = __half22float2(*(const __half2*)&pv.y);
        lh.x = lae(c01.x + lh.x, v01.x);
        lh.y = lae(c01.y + lh.y, v01.y);
        lh.z = lae(c23.x + lh.z, v23.x);
        lh.w = lae(c23.y + lh.w, v23.y);
        hv.x = __expf(lh.x); hv.y = __expf(lh.y);
        hv.z = __expf(lh.z); hv.w = __expf(lh.w);
        __half2 h2[2] = { __floats2half2_rn(hv.x, hv.y), __floats2half2_rn(hv.z, hv.w) };
        *(uint2*)(g_hh + base) = *(uint2*)h2;
        base += HID;
    }
    if (cid == NCH - 1)
        *(float4*)(out_hn + b * HID + ch) = hv;
}

// ---------------------------------------------------------------------------
// Launch. Inputs: x f32 (8,8192,512) | is_init bool(8) | W_hg f32 (1024,512)
// | W_out f32 (512,512). Output: out f32 (B,S,O) ++ h_n f32 (B,1,H).
// ---------------------------------------------------------------------------
extern "C" void kernel_launch(void* const* d_in, const int* in_sizes, int n_in,
                              void* d_out, int out_size) {
    (void)in_sizes; (void)n_in; (void)out_size;
    const float* x    = (const float*)d_in[0];
    const float* Whg  = (const float*)d_in[2];
    const float* Wout = (const float*)d_in[3];
    float* out    = (float*)d_out;
    float* out_hn = out + (size_t)MROWS * OUTD;

    cudaFuncSetAttribute((const void*)gemm1_mma,
                         cudaFuncAttributeMaxDynamicSharedMemorySize, SMEM_BYTES);
    cudaFuncSetAttribute((const void*)gemm2_mma,
                         cudaFuncAttributeMaxDynamicSharedMemorySize, SMEM_BYTES);

    __half *xh, *wh, *wo;
    cudaGetSymbolAddress((void**)&xh, g_xh);
    cudaGetSymbolAddress((void**)&wh, g_wh);
    cudaGetSymbolAddress((void**)&wo, g_wo);

    // fp16 conversion prepass
    cvt_half<<<(MROWS * (size_t)DIM) / 4 / 256, 256>>>(x, xh);
    cvt_half<<<(2 * HID * (size_t)DIM) / 4 / 256, 256>>>(Whg, wh);
    cvt_half<<<(OUTD * (size_t)HID) / 4 / 256, 256>>>(Wout, wo);

    // GEMM1 (fp16, kc=64, 3-stage) + fused lc/lv (fp16) + pass1
    gemm1_mma<<<dim3(HID / 64, MROWS / 128), 256, SMEM_BYTES>>>();

    // scan: pass3 with fused pass2 (per-block prefix from L2)
    scan_pass3<<<dim3(NCH, BATCH), 128>>>(out_hn);

    // GEMM2 (fp16, kc=64, 3-stage)
    gemm2_mma<<<dim3(OUTD / 128, MROWS / 128), 256, SMEM_BYTES>>>(out);
}

// round 12
// speedup vs baseline: 2.7736x; 1.0813x over previous
#include <cuda_runtime.h>
#include <cuda_fp16.h>
#include <cstdint>
#include <math.h>

// Problem dimensions (fixed by the reference)
#define BATCH 8
#define SEQ   8192
#define DIM   512
#define HID   512
#define OUTD  512
#define MROWS (BATCH*SEQ)      // 65536
#define CHUNK 128
#define NCH   (SEQ/CHUNK)      // 64

// ---------------------------------------------------------------------------
// Device scratch (no runtime allocation allowed)
// ---------------------------------------------------------------------------
static __device__ __half g_lch[(size_t)MROWS*HID];      // log_coeffs (fp16)
static __device__ __half g_lvh[(size_t)MROWS*HID];      // log_values (fp16)
static __device__ float g_A  [(size_t)BATCH*NCH*HID];   // chunk sum log_coeffs
static __device__ float g_LVc[(size_t)BATCH*NCH*HID];   // chunk log-value
static __device__ __half g_xh [(size_t)MROWS*DIM];      // x     (fp16)
static __device__ __half g_hh [(size_t)MROWS*HID];      // h     (fp16)
static __device__ __half g_wh [(size_t)2*HID*DIM];      // W_hg  (fp16)
static __device__ __half g_wo [(size_t)OUTD*HID];       // W_out (fp16)

// ---------------------------------------------------------------------------
// PTX helpers (sm_80+ only; no 'a'-suffix features)
// ---------------------------------------------------------------------------
__device__ __forceinline__ uint32_t smem_u32(const void* p) {
    uint32_t a;
    asm("{ .reg .u64 t; cvta.to.shared.u64 t, %1; cvt.u32.u64 %0, t; }" : "=r"(a) : "l"(p));
    return a;
}

#define CP_ASYNC16(dst, src) \
    asm volatile("cp.async.cg.shared.global [%0], [%1], 16;" :: "r"(dst), "l"(src))
#define CP_COMMIT() asm volatile("cp.async.commit_group;" ::: "memory")
#define CP_WAIT(N)  asm volatile("cp.async.wait_group %0;" :: "n"(N) : "memory")

#define LDMX4(r0, r1, r2, r3, a) \
    asm volatile("ldmatrix.sync.aligned.m8n8.x4.shared.b16 {%0,%1,%2,%3}, [%4];" \
        : "=r"(r0), "=r"(r1), "=r"(r2), "=r"(r3) : "r"(a))

// fp16 MMA, fp32 accumulate
#define MMA16816(c0, c1, c2, c3, a0, a1, a2, a3, b0, b1) \
    asm volatile("mma.sync.aligned.m16n8k16.row.col.f32.f16.f16.f32 " \
        "{%0,%1,%2,%3}, {%4,%5,%6,%7}, {%8,%9}, {%0,%1,%2,%3};" \
        : "+f"(c0), "+f"(c1), "+f"(c2), "+f"(c3) \
        : "r"(a0), "r"(a1), "r"(a2), "r"(a3), "r"(b0), "r"(b1))

// ---------------------------------------------------------------------------
// Math helpers (fast MUFU path)
// ---------------------------------------------------------------------------
__device__ __forceinline__ float sp_f(float x) {
    return fmaxf(x, 0.0f) + __logf(1.0f + __expf(-fabsf(x)));
}
__device__ __forceinline__ float lae(float a, float b) {
    float m = fmaxf(a, b);
    return m + __logf(1.0f + __expf(-fabsf(a - b)));
}

// ---------------------------------------------------------------------------
// Single fused fp32 -> fp16 conversion for x, W_hg, W_out
// ---------------------------------------------------------------------------
#define NX4 ((size_t)MROWS*DIM/4)          // 8388608
#define NW4 ((size_t)2*HID*DIM/4)          // 131072
#define NO4 ((size_t)OUTD*HID/4)           // 65536

__global__ __launch_bounds__(256) void cvt_all(const float* __restrict__ x,
                                               const float* __restrict__ Whg,
                                               const float* __restrict__ Wout) {
    const size_t i = (size_t)blockIdx.x * blockDim.x + threadIdx.x;
    const float* src;
    __half* dst;
    size_t k;
    if (i < NX4)            { src = x;    dst = g_xh; k = i; }
    else if (i < NX4 + NW4) { src = Whg;  dst = g_wh; k = i - NX4; }
    else                    { src = Wout; dst = g_wo; k = i - NX4 - NW4; }
    float4 v = ((const float4*)src)[k];
    ((__half2*)dst)[2*k]   = __floats2half2_rn(v.x, v.y);
    ((__half2*)dst)[2*k+1] = __floats2half2_rn(v.z, v.w);
}

// ---------------------------------------------------------------------------
// mma.sync GEMM mainloop. Block 128Mx128N, 256 threads (8 warps, warp tile
// 64x32), K=512, kc=64, THREE-stage cp.async pipeline, 2 CTAs/SM.
// Single fp16 product: acc += A*B (fp32 accumulate).
// SMEM stage: A [0,18432)  B [18432,36864), row stride 144B.
// INTERLEAVE (GEMM1): B-tile n-row r -> W_hg row (even: hidden, odd: gate).
// ---------------------------------------------------------------------------
#define ROWB    144
#define ARR_B   (128*ROWB)     // 18432
#define STG_B   (2*ARR_B)      // 36864
#define SMEM_BYTES (3*STG_B)   // 110592

template<bool INTERLEAVE>
__device__ __forceinline__ void gemm_mainloop(const __half* __restrict__ A,
                                              const __half* __restrict__ B,
                                              int m0, int nb, uint32_t sbase,
                                              float acc[4][4][4]) {
    const int tid  = threadIdx.x;
    const int lane = tid & 31;
    const int wid  = tid >> 5;
    const int wm   = (wid >> 2) * 64;   // warp M offset (0/64)
    const int wn   = (wid & 3) * 32;    // warp N offset (0/32/64/96)

#pragma unroll
    for (int mi = 0; mi < 4; mi++)
#pragma unroll
        for (int ni = 0; ni < 4; ni++)
#pragma unroll
            for (int e = 0; e < 4; e++) acc[mi][ni][e] = 0.0f;

    // Hoisted, lane-invariant ldmatrix offsets (per-step addr = st + off + s*32)
    uint32_t a_off[4], b_off[2];
#pragma unroll
    for (int mi = 0; mi < 4; mi++)
        a_off[mi] = (uint32_t)((wm + mi * 16 + (lane & 15)) * ROWB
                               + ((lane & 16) ? 16 : 0));
#pragma unroll
    for (int p = 0; p < 2; p++)
        b_off[p] = (uint32_t)(ARR_B
                   + (wn + p * 16 + (lane & 7) + ((lane & 16) ? 8 : 0)) * ROWB
                   + ((lane & 8) ? 16 : 0));

    // ---- stage loader: 8 cp.asyncs per thread (A, B) ----
    auto load_stage = [&](int j, int s) {
        const uint32_t st = sbase + s * STG_B;
        const int k0 = j * 64;
#pragma unroll
        for (int i = 0; i < 4; i++) {          // 1024 16B-chunks per array
            const int idx = tid + i * 256;
            const int r = idx >> 3, c = idx & 7;
            const uint32_t so = (uint32_t)(r * ROWB + c * 16);
            const size_t goa = (size_t)(m0 + r) * 512 + k0 + c * 8;
            CP_ASYNC16(st + so, (const void*)(A + goa));
            int wr;
            if (INTERLEAVE) wr = (r & 1) ? (512 + nb + (r >> 1)) : (nb + (r >> 1));
            else            wr = nb + r;
            const size_t gob = (size_t)wr * 512 + k0 + c * 8;
            CP_ASYNC16(st + ARR_B + so, (const void*)(B + gob));
        }
        CP_COMMIT();
    };

    load_stage(0, 0);
    load_stage(1, 1);

    for (int j = 0; j < 8; j++) {
        if (j < 7) { CP_WAIT(1); } else { CP_WAIT(0); }
        __syncthreads();            // all warps done with stage (j+2)%3's old data
        if (j + 2 < 8) load_stage(j + 2, (j + 2) % 3);

        const uint32_t st = sbase + (j % 3) * STG_B;
#pragma unroll
        for (int s = 0; s < 4; s++) {          // four k16 steps per stage
            const uint32_t sk = st + (uint32_t)(s * 32);
            // ---- issue ALL fragments first (6 LDSM back-to-back) ----
            uint32_t bh[4][2], ah[4][4];
            LDMX4(bh[0][0], bh[0][1], bh[1][0], bh[1][1], sk + b_off[0]);
            LDMX4(bh[2][0], bh[2][1], bh[3][0], bh[3][1], sk + b_off[1]);
#pragma unroll
            for (int mi = 0; mi < 4; mi++)
                LDMX4(ah[mi][0], ah[mi][1], ah[mi][2], ah[mi][3], sk + a_off[mi]);
            // ---- then 16 MMAs ----
#pragma unroll
            for (int mi = 0; mi < 4; mi++)
#pragma unroll
                for (int ni = 0; ni < 4; ni++)
                    MMA16816(acc[mi][ni][0], acc[mi][ni][1], acc[mi][ni][2], acc[mi][ni][3],
                             ah[mi][0], ah[mi][1], ah[mi][2], ah[mi][3],
                             bh[ni][0], bh[ni][1]);
        }
    }
    __syncthreads();
}

// ---------------------------------------------------------------------------
// GEMM1: hg = x @ W_hg^T, fused lc/lv epilogue (fp16 stores) AND fused
// per-chunk scan summaries (pass1). Block = 128 m-rows (one (batch,chunk))
// x 64 channels.
// ---------------------------------------------------------------------------
__global__ __launch_bounds__(256, 2)
void gemm1_mma() {
    extern __shared__ __align__(128) char smem[];
    const uint32_t sbase = smem_u32(smem);
    const int m0 = blockIdx.y * 128;
    const int nb = blockIdx.x * 64;

    float acc[4][4][4];
    gemm_mainloop<true>(g_xh, g_wh, m0, nb, sbase, acc);

    // Epilogue: compute lc/lv in regs, stage fp32 via smem (stride 76 floats).
    float* lcs = (float*)smem;                      // [128][76]
    float* lvs = lcs + 128 * 76;                    // [128][76]
    float* segA  = (float*)(smem + 77824);          // [4][64]
    float* segLV = segA + 256;                      // [4][64]
    const int tid = threadIdx.x, lane = tid & 31, wid = tid >> 5;
    const int wm = (wid >> 2) * 64;
    const int wn = (wid & 3) * 32;

#pragma unroll
    for (int mi = 0; mi < 4; mi++) {
#pragma unroll
        for (int ni = 0; ni < 4; ni++) {
            const int j  = (wn >> 1) + ni * 4 + (lane & 3);   // channel 0..63
            const int r0 = wm + mi * 16 + (lane >> 2);
#pragma unroll
            for (int e = 0; e < 2; e++) {
                const int r = r0 + e * 8;
                const float hv = acc[mi][ni][2*e];
                const float gv = acc[mi][ni][2*e + 1];
                const float lgv = (hv >= 0.0f) ? __logf(hv + 0.5f) : -sp_f(-hv);
                lcs[r * 76 + j] = -sp_f(gv);
                lvs[r * 76 + j] = lgv - sp_f(-gv);
            }
        }
    }
    __syncthreads();

    // Coalesced fp16 stores of lc/lv (4 halves = 8B per store)
    for (int idx = tid; idx < 2048; idx += 256) {
        const int r = idx >> 4, q = idx & 15;
        const size_t go = (size_t)(m0 + r) * HID + nb + q * 4;
        float4 vc = *(float4*)&lcs[r * 76 + q * 4];
        float4 vv = *(float4*)&lvs[r * 76 + q * 4];
        __half2 c2[2] = { __floats2half2_rn(vc.x, vc.y), __floats2half2_rn(vc.z, vc.w) };
        __half2 v2[2] = { __floats2half2_rn(vv.x, vv.y), __floats2half2_rn(vv.z, vv.w) };
        *(uint2*)(g_lch + go) = *(uint2*)c2;
        *(uint2*)(g_lvh + go) = *(uint2*)v2;
    }

    // Fused scan pass1: per-chunk (A, LV). 4 segments of 32 rows per channel.
    {
        const int j = tid & 63, seg = tid >> 6;
        float Acc = 0.0f, LV = -1e30f;
        for (int r = seg * 32; r < seg * 32 + 32; r++) {
            const float lc = lcs[r * 76 + j];
            const float lv = lvs[r * 76 + j];
            LV = lae(lc + LV, lv);
            Acc += lc;
        }
        segA [seg * 64 + j] = Acc;
        segLV[seg * 64 + j] = LV;
    }
    __syncthreads();
    if (tid < 64) {
        float Acc = segA[tid], LV = segLV[tid];
        for (int seg = 1; seg < 4; seg++) {
            const float A2  = segA [seg * 64 + tid];
            const float LV2 = segLV[seg * 64 + tid];
            LV = lae(LV + A2, LV2);    // compose: seg applied after prefix
            Acc += A2;
        }
        const int b = m0 / SEQ, c = (m0 % SEQ) / CHUNK;
        const size_t si = ((size_t)(b * NCH + c)) * HID + nb + tid;
        g_A[si]   = Acc;
        g_LVc[si] = LV;
    }
}

// ---------------------------------------------------------------------------
// GEMM2: out = h @ W_out^T. Grid: (OUTD/128, MROWS/128). Direct f32x2 stores.
// ---------------------------------------------------------------------------
__global__ __launch_bounds__(256, 2)
void gemm2_mma(float* __restrict__ out) {
    extern __shared__ __align__(128) char smem[];
    const uint32_t sbase = smem_u32(smem);
    const int m0 = blockIdx.y * 128;
    const int nb = blockIdx.x * 128;

    float acc[4][4][4];
    gemm_mainloop<false>(g_hh, g_wo, m0, nb, sbase, acc);

    const int tid = threadIdx.x, lane = tid & 31, wid = tid >> 5;
    const int wm = (wid >> 2) * 64;
    const int wn = (wid & 3) * 32;

#pragma unroll
    for (int mi = 0; mi < 4; mi++) {
#pragma unroll
        for (int ni = 0; ni < 4; ni++) {
            const int col = nb + wn + ni * 8 + (lane & 3) * 2;
            const int r0  = m0 + wm + mi * 16 + (lane >> 2);
            *(float2*)(out + (size_t)r0 * OUTD + col)
                = make_float2(acc[mi][ni][0], acc[mi][ni][1]);
            *(float2*)(out + (size_t)(r0 + 8) * OUTD + col)
                = make_float2(acc[mi][ni][2], acc[mi][ni][3]);
        }
    }
}

// ---------------------------------------------------------------------------
// Scan pass3 (pass2 fused): block = one (batch, chunk); 128 threads x 4
// channels. Prefix from L2-resident g_A/g_LVc, then chunk replay with
// software-pipelined loads (prefetch t+1 while computing t).
// ---------------------------------------------------------------------------
__global__ __launch_bounds__(128) void scan_pass3(float* __restrict__ out_hn) {
    const int b = blockIdx.y, cid = blockIdx.x;
    const int ch = threadIdx.x * 4;

    // Fused pass2: prefix over chunks [0, cid)
    float4 lh = make_float4(-1e30f, -1e30f, -1e30f, -1e30f);
    size_t si = ((size_t)(b * NCH)) * HID + ch;
    for (int c = 0; c < cid; c++, si += HID) {
        const float4 A4 = *(const float4*)(g_A + si);
        const float4 L4 = *(const float4*)(g_LVc + si);
        lh.x = lae(A4.x + lh.x, L4.x);
        lh.y = lae(A4.y + lh.y, L4.y);
        lh.z = lae(A4.z + lh.z, L4.z);
        lh.w = lae(A4.w + lh.w, L4.w);
    }

    // Chunk replay, software pipelined
    size_t base = ((size_t)(b * SEQ + cid * CHUNK)) * HID + ch;
    float4 hv = make_float4(0.f, 0.f, 0.f, 0.f);
    uint2 pc = *(const uint2*)(g_lch + base);
    uint2 pv = *(const uint2*)(g_lvh + base);
#pragma unroll 4
    for (int t = 0; t < CHUNK; t++) {
        uint2 npc, npv;
        if (t + 1 < CHUNK) {
            npc = *(const uint2*)(g_lch + base + HID);
            npv = *(const uint2*)(g_lvh + base + HID);
        }
        const float2 c01 = __half22float2(*(const __half2*)&pc.x);
        const float2 c23 = __half22float2(*(const __half2*)&pc.y);
        const float2 v01 = __half22float2(*(const __half2*)&pv.x);
        const float2 v23 = __half22float2(*(const __half2*)&pv.y);
        lh.x = lae(c01.x + lh.x, v01.x);
        lh.y = lae(c01.y + lh.y, v01.y);
        lh.z = lae(c23.x + lh.z, v23.x);
        lh.w = lae(c23.y + lh.w, v23.y);
        hv.x = __expf(lh.x); hv.y = __expf(lh.y);
        hv.z = __expf(lh.z); hv.w = __expf(lh.w);
        __half2 h2[2] = { __floats2half2_rn(hv.x, hv.y), __floats2half2_rn(hv.z, hv.w) };
        *(uint2*)(g_hh + base) = *(uint2*)h2;
        pc = npc; pv = npv;
        base += HID;
    }
    if (cid == NCH - 1)
        *(float4*)(out_hn + b * HID + ch) = hv;
}

// ---------------------------------------------------------------------------
// Launch. Inputs: x f32 (8,8192,512) | is_init bool(8) | W_hg f32 (1024,512)
// | W_out f32 (512,512). Output: out f32 (B,S,O) ++ h_n f32 (B,1,H).
// ---------------------------------------------------------------------------
extern "C" void kernel_launch(void* const* d_in, const int* in_sizes, int n_in,
                              void* d_out, int out_size) {
    (void)in_sizes; (void)n_in; (void)out_size;
    const float* x    = (const float*)d_in[0];
    const float* Whg  = (const float*)d_in[2];
    const float* Wout = (const float*)d_in[3];
    float* out    = (float*)d_out;
    float* out_hn = out + (size_t)MROWS * OUTD;

    cudaFuncSetAttribute((const void*)gemm1_mma,
                         cudaFuncAttributeMaxDynamicSharedMemorySize, SMEM_BYTES);
    cudaFuncSetAttribute((const void*)gemm2_mma,
                         cudaFuncAttributeMaxDynamicSharedMemorySize, SMEM_BYTES);

    // single fused fp16 conversion (x + both weights)
    cvt_all<<<(unsigned)((NX4 + NW4 + NO4) / 256), 256>>>(x, Whg, Wout);

    // GEMM1 (fp16, kc=64, 3-stage) + fused lc/lv (fp16) + pass1
    gemm1_mma<<<dim3(HID / 64, MROWS / 128), 256, SMEM_BYTES>>>();

    // scan: pass3 with fused pass2 (per-block prefix from L2)
    scan_pass3<<<dim3(NCH, BATCH), 128>>>(out_hn);

    // GEMM2 (fp16, kc=64, 3-stage)
    gemm2_mma<<<dim3(OUTD / 128, MROWS / 128), 256, SMEM_BYTES>>>(out);
}

// round 13
// speedup vs baseline: 2.7816x; 1.0029x over previous
#include <cuda_runtime.h>
#include <cuda_fp16.h>
#include <cstdint>
#include <math.h>

// Problem dimensions (fixed by the reference)
#define BATCH 8
#define SEQ   8192
#define DIM   512
#define HID   512
#define OUTD  512
#define MROWS (BATCH*SEQ)      // 65536
#define HCH   64               // half-chunk rows (scan granularity)
#define NHC   (SEQ/HCH)        // 128 half-chunks

// ---------------------------------------------------------------------------
// Device scratch (no runtime allocation allowed)
// ---------------------------------------------------------------------------
static __device__ __half g_lch[(size_t)MROWS*HID];      // log_coeffs (fp16)
static __device__ __half g_lvh[(size_t)MROWS*HID];      // log_values (fp16)
static __device__ float g_A  [(size_t)BATCH*NHC*HID];   // half-chunk sum log_coeffs
static __device__ float g_LVc[(size_t)BATCH*NHC*HID];   // half-chunk log-value
static __device__ __half g_xh [(size_t)MROWS*DIM];      // x     (fp16)
static __device__ __half g_hh [(size_t)MROWS*HID];      // h     (fp16)
static __device__ __half g_wh [(size_t)2*HID*DIM];      // W_hg  (fp16)
static __device__ __half g_wo [(size_t)OUTD*HID];       // W_out (fp16)

// ---------------------------------------------------------------------------
// PTX helpers (sm_80+ only; no 'a'-suffix features)
// ---------------------------------------------------------------------------
__device__ __forceinline__ uint32_t smem_u32(const void* p) {
    uint32_t a;
    asm("{ .reg .u64 t; cvta.to.shared.u64 t, %1; cvt.u32.u64 %0, t; }" : "=r"(a) : "l"(p));
    return a;
}

#define CP_ASYNC16(dst, src) \
    asm volatile("cp.async.cg.shared.global [%0], [%1], 16;" :: "r"(dst), "l"(src))
#define CP_COMMIT() asm volatile("cp.async.commit_group;" ::: "memory")
#define CP_WAIT(N)  asm volatile("cp.async.wait_group %0;" :: "n"(N) : "memory")

#define LDMX4(r0, r1, r2, r3, a) \
    asm volatile("ldmatrix.sync.aligned.m8n8.x4.shared.b16 {%0,%1,%2,%3}, [%4];" \
        : "=r"(r0), "=r"(r1), "=r"(r2), "=r"(r3) : "r"(a))

// fp16 MMA, fp32 accumulate
#define MMA16816(c0, c1, c2, c3, a0, a1, a2, a3, b0, b1) \
    asm volatile("mma.sync.aligned.m16n8k16.row.col.f32.f16.f16.f32 " \
        "{%0,%1,%2,%3}, {%4,%5,%6,%7}, {%8,%9}, {%0,%1,%2,%3};" \
        : "+f"(c0), "+f"(c1), "+f"(c2), "+f"(c3) \
        : "r"(a0), "r"(a1), "r"(a2), "r"(a3), "r"(b0), "r"(b1))

// ---------------------------------------------------------------------------
// Math helpers (fast MUFU path)
// ---------------------------------------------------------------------------
__device__ __forceinline__ float sp_f(float x) {
    return fmaxf(x, 0.0f) + __logf(1.0f + __expf(-fabsf(x)));
}
__device__ __forceinline__ float lae(float a, float b) {
    float m = fmaxf(a, b);
    return m + __logf(1.0f + __expf(-fabsf(a - b)));
}

// ---------------------------------------------------------------------------
// Single fused fp32 -> fp16 conversion for x, W_hg, W_out
// ---------------------------------------------------------------------------
#define NX4 ((size_t)MROWS*DIM/4)          // 8388608
#define NW4 ((size_t)2*HID*DIM/4)          // 131072
#define NO4 ((size_t)OUTD*HID/4)           // 65536

__global__ __launch_bounds__(256) void cvt_all(const float* __restrict__ x,
                                               const float* __restrict__ Whg,
                                               const float* __restrict__ Wout) {
    const size_t i = (size_t)blockIdx.x * blockDim.x + threadIdx.x;
    const float* src;
    __half* dst;
    size_t k;
    if (i < NX4)            { src = x;    dst = g_xh; k = i; }
    else if (i < NX4 + NW4) { src = Whg;  dst = g_wh; k = i - NX4; }
    else                    { src = Wout; dst = g_wo; k = i - NX4 - NW4; }
    float4 v = ((const float4*)src)[k];
    ((__half2*)dst)[2*k]   = __floats2half2_rn(v.x, v.y);
    ((__half2*)dst)[2*k+1] = __floats2half2_rn(v.z, v.w);
}

// ---------------------------------------------------------------------------
// mma.sync GEMM mainloop. Block 64Mx128N, 128 threads (4 warps, warp tile
// 64x32), K=512, kc=64, 2-stage cp.async pipeline, 4 CTAs/SM (four
// INDEPENDENT barrier domains per SM -> convoy-free tensor-pipe coverage).
// Single fp16 product: acc += A*B (fp32 accumulate).
// SMEM stage: A [0,9216)  B [9216,27648), row stride 144B.
// INTERLEAVE (GEMM1): B-tile n-row r -> W_hg row (even: hidden, odd: gate).
// ---------------------------------------------------------------------------
#define ROWB    144
#define ARR_A   (64*ROWB)       // 9216
#define ARR_BT  (128*ROWB)      // 18432
#define STG_B   (ARR_A+ARR_BT)  // 27648
#define SMEM_BYTES (2*STG_B)    // 55296

template<bool INTERLEAVE>
__device__ __forceinline__ void gemm_mainloop(const __half* __restrict__ A,
                                              const __half* __restrict__ B,
                                              int m0, int nb, uint32_t sbase,
                                              float acc[4][4][4]) {
    const int tid  = threadIdx.x;
    const int lane = tid & 31;
    const int wid  = tid >> 5;          // 0..3
    const int wn   = wid * 32;          // warp N offset

#pragma unroll
    for (int mi = 0; mi < 4; mi++)
#pragma unroll
        for (int ni = 0; ni < 4; ni++)
#pragma unroll
            for (int e = 0; e < 4; e++) acc[mi][ni][e] = 0.0f;

    // Hoisted, lane-invariant ldmatrix offsets (per-step addr = st + off + s*32)
    uint32_t a_off[4], b_off[2];
#pragma unroll
    for (int mi = 0; mi < 4; mi++)
        a_off[mi] = (uint32_t)((mi * 16 + (lane & 15)) * ROWB
                               + ((lane & 16) ? 16 : 0));
#pragma unroll
    for (int p = 0; p < 2; p++)
        b_off[p] = (uint32_t)(ARR_A
                   + (wn + p * 16 + (lane & 7) + ((lane & 16) ? 8 : 0)) * ROWB
                   + ((lane & 8) ? 16 : 0));

    // ---- stage loader: 12 cp.asyncs per thread (A:4, B:8) ----
    auto load_stage = [&](int j, int s) {
        const uint32_t st = sbase + s * STG_B;
        const int k0 = j * 64;
#pragma unroll
        for (int i = 0; i < 4; i++) {          // A: 512 16B-chunks
            const int idx = tid + i * 128;
            const int r = idx >> 3, c = idx & 7;
            CP_ASYNC16(st + (uint32_t)(r * ROWB + c * 16),
                       (const void*)(A + (size_t)(m0 + r) * 512 + k0 + c * 8));
        }
#pragma unroll
        for (int i = 0; i < 8; i++) {          // B: 1024 16B-chunks
            const int idx = tid + i * 128;
            const int r = idx >> 3, c = idx & 7;
            int wr;
            if (INTERLEAVE) wr = (r & 1) ? (512 + nb + (r >> 1)) : (nb + (r >> 1));
            else            wr = nb + r;
            CP_ASYNC16(st + (uint32_t)(ARR_A + r * ROWB + c * 16),
                       (const void*)(B + (size_t)wr * 512 + k0 + c * 8));
        }
        CP_COMMIT();
    };

    load_stage(0, 0);

    for (int j = 0; j < 8; j++) {
        CP_WAIT(0);
        __syncthreads();                 // stage j visible; stage (j+1)&1 free
        if (j + 1 < 8) load_stage(j + 1, (j + 1) & 1);

        const uint32_t st = sbase + (j & 1) * STG_B;
#pragma unroll
        for (int s = 0; s < 4; s++) {    // four k16 steps per stage
            const uint32_t sk = st + (uint32_t)(s * 32);
            uint32_t bh[4][2], ah[4][4];
            LDMX4(bh[0][0], bh[0][1], bh[1][0], bh[1][1], sk + b_off[0]);
            LDMX4(bh[2][0], bh[2][1], bh[3][0], bh[3][1], sk + b_off[1]);
#pragma unroll
            for (int mi = 0; mi < 4; mi++)
                LDMX4(ah[mi][0], ah[mi][1], ah[mi][2], ah[mi][3], sk + a_off[mi]);
#pragma unroll
            for (int mi = 0; mi < 4; mi++)
#pragma unroll
                for (int ni = 0; ni < 4; ni++)
                    MMA16816(acc[mi][ni][0], acc[mi][ni][1], acc[mi][ni][2], acc[mi][ni][3],
                             ah[mi][0], ah[mi][1], ah[mi][2], ah[mi][3],
                             bh[ni][0], bh[ni][1]);
        }
    }
    __syncthreads();                     // before epilogue smem reuse
}

// ---------------------------------------------------------------------------
// GEMM1: hg = x @ W_hg^T, fused lc/lv epilogue (fp16 stores) AND fused
// half-chunk scan summaries. Block = 64 m-rows (one (batch, half-chunk))
// x 64 channels. Grid (8, 1024).
// ---------------------------------------------------------------------------
__global__ __launch_bounds__(128, 4)
void gemm1_mma() {
    extern __shared__ __align__(128) char smem[];
    const uint32_t sbase = smem_u32(smem);
    const int m0 = blockIdx.y * 64;
    const int nb = blockIdx.x * 64;

    float acc[4][4][4];
    gemm_mainloop<true>(g_xh, g_wh, m0, nb, sbase, acc);

    // Epilogue: compute lc/lv in regs, stage fp32 via smem (stride 76 floats).
    float* lcs = (float*)smem;                      // [64][76]
    float* lvs = lcs + 64 * 76;                     // [64][76]
    float* segA  = (float*)(smem + 40960);          // [2][64]
    float* segLV = segA + 128;                      // [2][64]
    const int tid = threadIdx.x, lane = tid & 31, wid = tid >> 5;
    const int wn = wid * 32;

#pragma unroll
    for (int mi = 0; mi < 4; mi++) {
#pragma unroll
        for (int ni = 0; ni < 4; ni++) {
            const int j  = (wn >> 1) + ni * 4 + (lane & 3);   // channel 0..63
            const int r0 = mi * 16 + (lane >> 2);
#pragma unroll
            for (int e = 0; e < 2; e++) {
                const int r = r0 + e * 8;
                const float hv = acc[mi][ni][2*e];
                const float gv = acc[mi][ni][2*e + 1];
                const float lgv = (hv >= 0.0f) ? __logf(hv + 0.5f) : -sp_f(-hv);
                lcs[r * 76 + j] = -sp_f(gv);
                lvs[r * 76 + j] = lgv - sp_f(-gv);
            }
        }
    }
    __syncthreads();

    // Coalesced fp16 stores of lc/lv (4 halves = 8B per store)
    for (int idx = tid; idx < 1024; idx += 128) {
        const int r = idx >> 4, q = idx & 15;
        const size_t go = (size_t)(m0 + r) * HID + nb + q * 4;
        float4 vc = *(float4*)&lcs[r * 76 + q * 4];
        float4 vv = *(float4*)&lvs[r * 76 + q * 4];
        __half2 c2[2] = { __floats2half2_rn(vc.x, vc.y), __floats2half2_rn(vc.z, vc.w) };
        __half2 v2[2] = { __floats2half2_rn(vv.x, vv.y), __floats2half2_rn(vv.z, vv.w) };
        *(uint2*)(g_lch + go) = *(uint2*)c2;
        *(uint2*)(g_lvh + go) = *(uint2*)v2;
    }

    // Fused scan summaries: per half-chunk (A, LV). 2 segments of 32 rows.
    {
        const int j = tid & 63, seg = tid >> 6;
        float Acc = 0.0f, LV = -1e30f;
        for (int r = seg * 32; r < seg * 32 + 32; r++) {
            const float lc = lcs[r * 76 + j];
            const float lv = lvs[r * 76 + j];
            LV = lae(lc + LV, lv);
            Acc += lc;
        }
        segA [seg * 64 + j] = Acc;
        segLV[seg * 64 + j] = LV;
    }
    __syncthreads();
    if (tid < 64) {
        const float A2  = segA [64 + tid];
        const float LV2 = segLV[64 + tid];
        float Acc = segA[tid] + A2;
        float LV  = lae(segLV[tid] + A2, LV2);
        const int b = m0 / SEQ, hc = (m0 % SEQ) / HCH;
        const size_t si = ((size_t)(b * NHC + hc)) * HID + nb + tid;
        g_A[si]   = Acc;
        g_LVc[si] = LV;
    }
}

// ---------------------------------------------------------------------------
// GEMM2: out = h @ W_out^T. Block 64x128, grid (4, 1024). f32x2 stores.
// ---------------------------------------------------------------------------
__global__ __launch_bounds__(128, 4)
void gemm2_mma(float* __restrict__ out) {
    extern __shared__ __align__(128) char smem[];
    const uint32_t sbase = smem_u32(smem);
    const int m0 = blockIdx.y * 64;
    const int nb = blockIdx.x * 128;

    float acc[4][4][4];
    gemm_mainloop<false>(g_hh, g_wo, m0, nb, sbase, acc);

    const int lane = threadIdx.x & 31, wid = threadIdx.x >> 5;
    const int wn = wid * 32;

#pragma unroll
    for (int mi = 0; mi < 4; mi++) {
#pragma unroll
        for (int ni = 0; ni < 4; ni++) {
            const int col = nb + wn + ni * 8 + (lane & 3) * 2;
            const int r0  = m0 + mi * 16 + (lane >> 2);
            *(float2*)(out + (size_t)r0 * OUTD + col)
                = make_float2(acc[mi][ni][0], acc[mi][ni][1]);
            *(float2*)(out + (size_t)(r0 + 8) * OUTD + col)
                = make_float2(acc[mi][ni][2], acc[mi][ni][3]);
        }
    }
}

// ---------------------------------------------------------------------------
// Scan pass3 (pass2 fused): block = one (batch, half-chunk); 128 threads x 4
// channels. Prefix from L2-resident g_A/g_LVc, then 64-row replay with
// software-pipelined loads. Emits fp16 h.
// ---------------------------------------------------------------------------
__global__ __launch_bounds__(128) void scan_pass3(float* __restrict__ out_hn) {
    const int b = blockIdx.y, cid = blockIdx.x;       // cid 0..127
    const int ch = threadIdx.x * 4;

    // Fused pass2: prefix over half-chunks [0, cid)
    float4 lh = make_float4(-1e30f, -1e30f, -1e30f, -1e30f);
    size_t si = ((size_t)(b * NHC)) * HID + ch;
    for (int c = 0; c < cid; c++, si += HID) {
        const float4 A4 = *(const float4*)(g_A + si);
        const float4 L4 = *(const float4*)(g_LVc + si);
        lh.x = lae(A4.x + lh.x, L4.x);
        lh.y = lae(A4.y + lh.y, L4.y);
        lh.z = lae(A4.z + lh.z, L4.z);
        lh.w = lae(A4.w + lh.w, L4.w);
    }

    // Half-chunk replay, software pipelined
    size_t base = ((size_t)(b * SEQ + cid * HCH)) * HID + ch;
    float4 hv = make_float4(0.f, 0.f, 0.f, 0.f);
    uint2 pc = *(const uint2*)(g_lch + base);
    uint2 pv = *(const uint2*)(g_lvh + base);
#pragma unroll 4
    for (int t = 0; t < HCH; t++) {
        uint2 npc, npv;
        if (t + 1 < HCH) {
            npc = *(const uint2*)(g_lch + base + HID);
            npv = *(const uint2*)(g_lvh + base + HID);
        }
        const float2 c01 = __half22float2(*(const __half2*)&pc.x);
        const float2 c23 = __half22float2(*(const __half2*)&pc.y);
        const float2 v01 = __half22float2(*(const __half2*)&pv.x);
        const float2 v23 = __half22float2(*(const __half2*)&pv.y);
        lh.x = lae(c01.x + lh.x, v01.x);
        lh.y = lae(c01.y + lh.y, v01.y);
        lh.z = lae(c23.x + lh.z, v23.x);
        lh.w = lae(c23.y + lh.w, v23.y);
        hv.x = __expf(lh.x); hv.y = __expf(lh.y);
        hv.z = __expf(lh.z); hv.w = __expf(lh.w);
        __half2 h2[2] = { __floats2half2_rn(hv.x, hv.y), __floats2half2_rn(hv.z, hv.w) };
        *(uint2*)(g_hh + base) = *(uint2*)h2;
        pc = npc; pv = npv;
        base += HID;
    }
    if (cid == NHC - 1)
        *(float4*)(out_hn + b * HID + ch) = hv;
}

// ---------------------------------------------------------------------------
// Launch. Inputs: x f32 (8,8192,512) | is_init bool(8) | W_hg f32 (1024,512)
// | W_out f32 (512,512). Output: out f32 (B,S,O) ++ h_n f32 (B,1,H).
// ---------------------------------------------------------------------------
extern "C" void kernel_launch(void* const* d_in, const int* in_sizes, int n_in,
                              void* d_out, int out_size) {
    (void)in_sizes; (void)n_in; (void)out_size;
    const float* x    = (const float*)d_in[0];
    const float* Whg  = (const float*)d_in[2];
    const float* Wout = (const float*)d_in[3];
    float* out    = (float*)d_out;
    float* out_hn = out + (size_t)MROWS * OUTD;

    cudaFuncSetAttribute((const void*)gemm1_mma,
                         cudaFuncAttributeMaxDynamicSharedMemorySize, SMEM_BYTES);
    cudaFuncSetAttribute((const void*)gemm2_mma,
                         cudaFuncAttributeMaxDynamicSharedMemorySize, SMEM_BYTES);

    // single fused fp16 conversion (x + both weights)
    cvt_all<<<(unsigned)((NX4 + NW4 + NO4) / 256), 256>>>(x, Whg, Wout);

    // GEMM1 (fp16, kc=64, 64x128 tiles, 4 CTAs/SM) + fused lc/lv + summaries
    gemm1_mma<<<dim3(HID / 64, MROWS / 64), 128, SMEM_BYTES>>>();

    // scan: half-chunk replay with fused prefix
    scan_pass3<<<dim3(NHC, BATCH), 128>>>(out_hn);

    // GEMM2 (fp16, kc=64, 64x128 tiles, 4 CTAs/SM)
    gemm2_mma<<<dim3(OUTD / 128, MROWS / 64), 128, SMEM_BYTES>>>(out);
}